// round 5
// baseline (speedup 1.0000x reference)
#include <cuda_runtime.h>
#include <cstdint>
#include <cstddef>

// ---------------------------------------------------------------------------
// Problem constants
// ---------------------------------------------------------------------------
#define BB     16
#define CDIM   256
#define HDIM   64
#define WDIM   64
#define NHKD   128
#define DHD    512
#define NPIX   65536        // BB*HDIM*WDIM
#define NAX    1024         // BB*64
#define NHEADS 8
#define KEYD   16
#define DV     64
#define ATTN_SCALE 0.25f

// ---------------------------------------------------------------------------
// Scratch (device globals; no allocation allowed)
// ---------------------------------------------------------------------------
__device__ float g_xrp[CDIM * NAX];            // row means, packed [c][b*64+h]
__device__ float g_xcp[CDIM * NAX];            // col means, packed [c][b*64+w]
__device__ float g_qe[2][NHKD * NAX];
__device__ float g_ke[2][NHKD * NAX];
__device__ float g_ve[2][DHD * NAX];
__device__ float g_xx[2][DHD * NAX];           // attention output (pre-relu)
__device__ float g_rout[2][DHD * NAX];         // after w_row / w_col cbn
__device__ float g_A[(size_t)DHD * NPIX];      // relu(v + row + col), packed [m][n]
__device__ float g_g1[(size_t)CDIM * NPIX];    // gate after w_sc cbn, packed [c][n]
__device__ float g_g2[(size_t)CDIM * NPIX];    // relu(dw(g1)), packed [c][n]
__device__ float g_P[(size_t)CDIM * NPIX];     // proj output, packed [m][n]

// ---------------------------------------------------------------------------
// K1: row/col means of x -> packed [256][1024] layouts
// one block per (b, c) slab of 64x64
// ---------------------------------------------------------------------------
__global__ void mean_kernel(const float* __restrict__ x)
{
    __shared__ float s[64 * 65];               // padded to kill bank conflicts
    const int blk = blockIdx.x;                // b*256 + c
    const float* base = x + (size_t)blk * 4096;
    const int t = threadIdx.x;                 // 64 threads

    #pragma unroll
    for (int i = 0; i < 64; i++) {
        float v = base[i * 64 + t];            // coalesced
        s[i * 65 + t] = v;
    }
    __syncthreads();

    float rs = 0.f, cs = 0.f;
    #pragma unroll
    for (int i = 0; i < 64; i++) {
        rs += s[t * 65 + i];                   // row t  (over w)
        cs += s[i * 65 + t];                   // col t  (over h)
    }
    const int b = blk >> 8;
    const int c = blk & 255;
    g_xrp[c * NAX + b * 64 + t] = rs * (1.f / 64.f);
    g_xcp[c * NAX + b * 64 + t] = cs * (1.f / 64.f);
}

// ---------------------------------------------------------------------------
// Generic tiled fp32 GEMM: out = epilogue( W[M,K] @ X[K,N] )
//   64x64 tile, BK=16, 256 threads, 4x4 microtile, float4 smem traffic.
// MODE 0: X packed,           out = acc*s+b                        (packed)
// MODE 1: X packed + relu-in, out = acc*s+b                        (packed)
// MODE 2: X = x (BCHW, K=256) out = relu(acc*s+b + e0[h] + e1[w])  (packed)
// MODE 3: X = x (BCHW, K=256) out = acc*s+b                        (packed)
// MODE 4: X packed,           out = h_sigmoid(acc*s+b) * e0, scatter to BCHW
// ---------------------------------------------------------------------------
template <int MODE>
__global__ void gemm_kernel(const float* __restrict__ Wm,
                            const float* __restrict__ X,
                            const float* __restrict__ scale,
                            const float* __restrict__ bias,
                            float* __restrict__ out,
                            int M, int N, int K,
                            const float* __restrict__ e0,
                            const float* __restrict__ e1)
{
    __shared__ float Ws[16][68];   // row stride 272B (16B aligned)
    __shared__ float Xs[16][64];

    const int bm = blockIdx.y * 64;
    const int bn = blockIdx.x * 64;
    const int t  = threadIdx.x;          // 256
    const int ty = t >> 4;               // 0..15 -> rows ty*4..ty*4+3
    const int tx = t & 15;               // 0..15 -> cols tx*4..tx*4+3

    float acc[4][4];
    #pragma unroll
    for (int i = 0; i < 4; i++)
        #pragma unroll
        for (int j = 0; j < 4; j++) acc[i][j] = 0.f;

    for (int k0 = 0; k0 < K; k0 += 16) {
        // --- load W tile (64 rows x 16 k), transposed into smem ---
        {
            const int m  = t >> 2;           // 0..63
            const int kk = (t & 3) * 4;      // 0,4,8,12
            float4 wv = *reinterpret_cast<const float4*>(
                &Wm[(size_t)(bm + m) * K + k0 + kk]);
            Ws[kk + 0][m] = wv.x;
            Ws[kk + 1][m] = wv.y;
            Ws[kk + 2][m] = wv.z;
            Ws[kk + 3][m] = wv.w;
        }
        // --- load X tile (16 k x 64 n) ---
        {
            const int kk = t >> 4;           // 0..15
            const int nn = (t & 15) * 4;     // 0..60
            const int kg = k0 + kk;
            const int ng = bn + nn;
            float4 xv;
            if (MODE == 2 || MODE == 3) {
                const int b  = ng >> 12;
                const int hw = ng & 4095;
                xv = *reinterpret_cast<const float4*>(
                    &X[((size_t)b * CDIM + kg) * 4096 + hw]);
            } else {
                xv = *reinterpret_cast<const float4*>(&X[(size_t)kg * N + ng]);
            }
            if (MODE == 1) {
                xv.x = fmaxf(xv.x, 0.f); xv.y = fmaxf(xv.y, 0.f);
                xv.z = fmaxf(xv.z, 0.f); xv.w = fmaxf(xv.w, 0.f);
            }
            *reinterpret_cast<float4*>(&Xs[kk][nn]) = xv;
        }
        __syncthreads();

        #pragma unroll
        for (int kk = 0; kk < 16; kk++) {
            float4 a = *reinterpret_cast<const float4*>(&Ws[kk][ty * 4]);
            float4 b = *reinterpret_cast<const float4*>(&Xs[kk][tx * 4]);
            float av[4] = {a.x, a.y, a.z, a.w};
            float bv[4] = {b.x, b.y, b.z, b.w};
            #pragma unroll
            for (int i = 0; i < 4; i++)
                #pragma unroll
                for (int j = 0; j < 4; j++)
                    acc[i][j] += av[i] * bv[j];
        }
        __syncthreads();
    }

    // --- epilogue ---
    #pragma unroll
    for (int i = 0; i < 4; i++) {
        const int m = bm + ty * 4 + i;
        const float sc = scale[m];
        const float bi = bias[m];
        #pragma unroll
        for (int j = 0; j < 4; j++) {
            const int n = bn + tx * 4 + j;
            float v = acc[i][j] * sc + bi;
            if (MODE == 2) {
                const int b  = n >> 12;
                const int hw = n & 4095;
                v += e0[m * NAX + (b << 6) + (hw >> 6)];   // row_out[h]
                v += e1[m * NAX + (b << 6) + (hw & 63)];   // col_out[w]
                v = fmaxf(v, 0.f);
                out[(size_t)m * N + n] = v;
            } else if (MODE == 4) {
                float g = fminf(fmaxf(v + 3.f, 0.f), 6.f) * (1.f / 6.f);
                float o = g * e0[(size_t)m * N + n];
                const int b  = n >> 12;
                const int hw = n & 4095;
                out[((size_t)b * CDIM + m) * 4096 + hw] = o;   // NCHW scatter
            } else {
                out[(size_t)m * N + n] = v;
            }
        }
    }
}

// ---------------------------------------------------------------------------
// K3: axial attention. One block per (axis, b, head); 64 threads (one per n).
// ---------------------------------------------------------------------------
__device__ __forceinline__ float pos_interp(const float* __restrict__ p,
                                            int ch, int i)
{
    // interpolate pos[1,128,16] (length 16) to length 64, linear, no corners
    float c = (i + 0.5f) * 0.25f - 0.5f;
    c = fminf(fmaxf(c, 0.f), 15.f);
    int lo = (int)floorf(c);
    int hi = min(lo + 1, 15);
    float tt = c - (float)lo;
    const float* row = p + ch * 16;
    return row[lo] * (1.f - tt) + row[hi] * tt;
}

__global__ void attn_kernel(const float* __restrict__ pos_rowq,
                            const float* __restrict__ pos_rowk,
                            const float* __restrict__ pos_colq,
                            const float* __restrict__ pos_colk)
{
    const int blk  = blockIdx.x;          // axis*128 + b*8 + head
    const int axis = blk >> 7;
    const int b    = (blk >> 3) & 15;
    const int head = blk & 7;
    const float* pq = axis ? pos_colq : pos_rowq;
    const float* pk = axis ? pos_colk : pos_rowk;
    const float* qe = g_qe[axis];
    const float* ke = g_ke[axis];
    const float* ve = g_ve[axis];

    __shared__ float ks[KEYD][64];
    __shared__ float vs[DV][64];
    const int t = threadIdx.x;            // 64

    float qr[KEYD];
    #pragma unroll
    for (int c = 0; c < KEYD; c++) {
        const int ch = head * KEYD + c;
        ks[c][t] = ke[ch * NAX + b * 64 + t] + pos_interp(pk, ch, t);
        qr[c]    = qe[ch * NAX + b * 64 + t] + pos_interp(pq, ch, t);
    }
    #pragma unroll
    for (int d = 0; d < DV; d++)
        vs[d][t] = ve[(head * DV + d) * NAX + b * 64 + t];
    __syncthreads();

    float S[64];
    float mx = -1e30f;
    #pragma unroll
    for (int j = 0; j < 64; j++) {
        float s = 0.f;
        #pragma unroll
        for (int c = 0; c < KEYD; c++) s += qr[c] * ks[c][j];
        s *= ATTN_SCALE;
        S[j] = s;
        mx = fmaxf(mx, s);
    }
    float sum = 0.f;
    #pragma unroll
    for (int j = 0; j < 64; j++) {
        S[j] = __expf(S[j] - mx);
        sum += S[j];
    }
    const float inv = 1.f / sum;

    float* xo = g_xx[axis];
    #pragma unroll
    for (int d = 0; d < DV; d++) {
        float o = 0.f;
        #pragma unroll
        for (int j = 0; j < 64; j++) o += S[j] * vs[d][j];
        xo[(head * DV + d) * NAX + b * 64 + t] = o * inv;
    }
}

// ---------------------------------------------------------------------------
// K6b: depthwise 3x3 (SAME, zero pad) + affine + relu.  g1 -> g2
// ---------------------------------------------------------------------------
__global__ void dw_kernel(const float* __restrict__ wdw,
                          const float* __restrict__ sdw,
                          const float* __restrict__ bdw)
{
    const long long idx = (long long)blockIdx.x * blockDim.x + threadIdx.x;
    if (idx >= (long long)CDIM * NPIX) return;
    const int n = (int)(idx & (NPIX - 1));
    const int c = (int)(idx >> 16);
    const int b = n >> 12, hw = n & 4095;
    const int h = hw >> 6, w = hw & 63;
    const float* base = g_g1 + (size_t)c * NPIX + (size_t)b * 4096;
    const float* wk = wdw + c * 9;

    float acc = 0.f;
    #pragma unroll
    for (int dy = 0; dy < 3; dy++) {
        const int hh = h + dy - 1;
        if (hh < 0 || hh > 63) continue;
        #pragma unroll
        for (int dx = 0; dx < 3; dx++) {
            const int ww = w + dx - 1;
            if (ww < 0 || ww > 63) continue;
            acc += base[hh * 64 + ww] * wk[dy * 3 + dx];
        }
    }
    float v = acc * sdw[c] + bdw[c];
    g_g2[idx] = fmaxf(v, 0.f);
}

// ---------------------------------------------------------------------------
// Host launcher
// ---------------------------------------------------------------------------
extern "C" void kernel_launch(void* const* d_in, const int* in_sizes, int n_in,
                              void* d_out, int out_size)
{
    const float* x        = (const float*)d_in[0];
    const float* wq       = (const float*)d_in[1];
    const float* sq       = (const float*)d_in[2];
    const float* bq       = (const float*)d_in[3];
    const float* wk       = (const float*)d_in[4];
    const float* sk       = (const float*)d_in[5];
    const float* bk       = (const float*)d_in[6];
    const float* wv       = (const float*)d_in[7];
    const float* sv       = (const float*)d_in[8];
    const float* bv       = (const float*)d_in[9];
    const float* pos_rowq = (const float*)d_in[10];
    const float* pos_rowk = (const float*)d_in[11];
    const float* pos_colq = (const float*)d_in[12];
    const float* pos_colk = (const float*)d_in[13];
    const float* w_row    = (const float*)d_in[14];
    const float* s_row    = (const float*)d_in[15];
    const float* b_row    = (const float*)d_in[16];
    const float* w_col    = (const float*)d_in[17];
    const float* s_col    = (const float*)d_in[18];
    const float* b_col    = (const float*)d_in[19];
    const float* w_proj   = (const float*)d_in[20];
    const float* s_proj   = (const float*)d_in[21];
    const float* b_proj   = (const float*)d_in[22];
    const float* w_sc     = (const float*)d_in[23];
    const float* s_sc     = (const float*)d_in[24];
    const float* b_sc     = (const float*)d_in[25];
    const float* w_dw     = (const float*)d_in[26];
    const float* s_dw     = (const float*)d_in[27];
    const float* b_dw     = (const float*)d_in[28];
    const float* w_pw     = (const float*)d_in[29];
    const float* s_pw     = (const float*)d_in[30];
    const float* b_pw     = (const float*)d_in[31];

    float *p_xrp, *p_xcp, *p_qe, *p_ke, *p_ve, *p_xx, *p_rout;
    float *p_A, *p_g1, *p_g2, *p_P;
    cudaGetSymbolAddress((void**)&p_xrp,  g_xrp);
    cudaGetSymbolAddress((void**)&p_xcp,  g_xcp);
    cudaGetSymbolAddress((void**)&p_qe,   g_qe);
    cudaGetSymbolAddress((void**)&p_ke,   g_ke);
    cudaGetSymbolAddress((void**)&p_ve,   g_ve);
    cudaGetSymbolAddress((void**)&p_xx,   g_xx);
    cudaGetSymbolAddress((void**)&p_rout, g_rout);
    cudaGetSymbolAddress((void**)&p_A,    g_A);
    cudaGetSymbolAddress((void**)&p_g1,   g_g1);
    cudaGetSymbolAddress((void**)&p_g2,   g_g2);
    cudaGetSymbolAddress((void**)&p_P,    g_P);

    // K1: means
    mean_kernel<<<BB * CDIM, 64>>>(x);

    // K2: axis q/k/v projections on the mean vectors (tiny GEMMs)
    for (int axis = 0; axis < 2; axis++) {
        const float* Xax = axis ? p_xcp : p_xrp;
        gemm_kernel<0><<<dim3(NAX / 64, NHKD / 64), 256>>>(
            wq, Xax, sq, bq, p_qe + (size_t)axis * NHKD * NAX,
            NHKD, NAX, CDIM, nullptr, nullptr);
        gemm_kernel<0><<<dim3(NAX / 64, NHKD / 64), 256>>>(
            wk, Xax, sk, bk, p_ke + (size_t)axis * NHKD * NAX,
            NHKD, NAX, CDIM, nullptr, nullptr);
        gemm_kernel<0><<<dim3(NAX / 64, DHD / 64), 256>>>(
            wv, Xax, sv, bv, p_ve + (size_t)axis * DHD * NAX,
            DHD, NAX, CDIM, nullptr, nullptr);
    }

    // K3: axial attention (both axes)
    attn_kernel<<<2 * BB * NHEADS, 64>>>(pos_rowq, pos_rowk, pos_colq, pos_colk);

    // K4: w_row / w_col cbn on relu(xx)
    gemm_kernel<1><<<dim3(NAX / 64, DHD / 64), 256>>>(
        w_row, p_xx, s_row, b_row, p_rout,
        DHD, NAX, DHD, nullptr, nullptr);
    gemm_kernel<1><<<dim3(NAX / 64, DHD / 64), 256>>>(
        w_col, p_xx + (size_t)DHD * NAX, s_col, b_col, p_rout + (size_t)DHD * NAX,
        DHD, NAX, DHD, nullptr, nullptr);

    // K5: A = relu(v + row + col)   (big GEMM over all pixels)
    gemm_kernel<2><<<dim3(NPIX / 64, DHD / 64), 256>>>(
        wv, x, sv, bv, p_A,
        DHD, NPIX, CDIM, p_rout, p_rout + (size_t)DHD * NAX);

    // K5g: g1 = cbn(x, w_sc)
    gemm_kernel<3><<<dim3(NPIX / 64, CDIM / 64), 256>>>(
        w_sc, x, s_sc, b_sc, p_g1,
        CDIM, NPIX, CDIM, nullptr, nullptr);

    // K6a: P = cbn(A, w_proj)
    gemm_kernel<0><<<dim3(NPIX / 64, CDIM / 64), 256>>>(
        w_proj, p_A, s_proj, b_proj, p_P,
        CDIM, NPIX, DHD, nullptr, nullptr);

    // K6b: depthwise 3x3 + affine + relu
    dw_kernel<<<(CDIM * NPIX) / 256, 256>>>(w_dw, s_dw, b_dw);

    // K6c: out = h_sigmoid(cbn(g2, w_pw)) * P  (scatter to NCHW)
    gemm_kernel<4><<<dim3(NPIX / 64, CDIM / 64), 256>>>(
        w_pw, p_g2, s_pw, b_pw, (float*)d_out,
        CDIM, NPIX, CDIM, p_P, nullptr);
}

// round 11
// speedup vs baseline: 2.0481x; 2.0481x over previous
#include <cuda_runtime.h>
#include <cstdint>
#include <cstddef>

// ---------------------------------------------------------------------------
// Problem constants
// ---------------------------------------------------------------------------
#define BB     16
#define CDIM   256
#define HDIM   64
#define WDIM   64
#define NHKD   128
#define DHD    512
#define NPIX   65536        // BB*HDIM*WDIM
#define NAX    1024         // BB*64
#define NAX2   2048         // both axes packed
#define NHEADS 8
#define KEYD   16
#define DV     64
#define ATTN_SCALE 0.25f

// ---------------------------------------------------------------------------
// Scratch (device globals; no allocation allowed)
// ---------------------------------------------------------------------------
__device__ float g_xmean[CDIM * NAX2];         // [c][axis*1024 + b*64 + p]
__device__ float g_qe[NHKD * NAX2];
__device__ float g_ke[NHKD * NAX2];
__device__ float g_ve[DHD * NAX2];
__device__ float g_xx[2][DHD * NAX];           // attention output (pre-relu)
__device__ float g_rout[2][DHD * NAX];         // after w_row / w_col cbn
__device__ float g_A[(size_t)DHD * NPIX];      // relu(v + row + col), packed [m][n]
__device__ float g_g1[(size_t)CDIM * NPIX];    // gate after w_sc cbn, packed [c][n]
__device__ float g_g2[(size_t)CDIM * NPIX];    // relu(dw(g1)), packed [c][n]
__device__ float g_P[(size_t)CDIM * NPIX];     // proj output, packed [m][n]

// ---------------------------------------------------------------------------
// m16n8k8 tf32 mma.sync (sm_80+; valid at target sm_103)
// A row-major frag (4 regs), B col-major frag (2 regs), C/D f32 (4 regs)
// ---------------------------------------------------------------------------
__device__ __forceinline__ void mma_tf32(float* c, const uint32_t* a,
                                         const uint32_t* b)
{
    asm volatile(
        "mma.sync.aligned.m16n8k8.row.col.f32.tf32.tf32.f32 "
        "{%0,%1,%2,%3}, {%4,%5,%6,%7}, {%8,%9}, {%0,%1,%2,%3};"
        : "+f"(c[0]), "+f"(c[1]), "+f"(c[2]), "+f"(c[3])
        : "r"(a[0]), "r"(a[1]), "r"(a[2]), "r"(a[3]),
          "r"(b[0]), "r"(b[1]));
}

// round-to-nearest tf32 (top 19 bits), result reinterpretable as f32
__device__ __forceinline__ uint32_t tf32_rna(float x)
{
    uint32_t r;
    asm("cvt.rna.tf32.f32 %0, %1;" : "=r"(r) : "f"(x));
    return r;
}

// split x into hi (tf32, rna) + lo (residual, raw f32 bits; HW-truncated)
__device__ __forceinline__ void tf32_split(float x, uint32_t& hi, uint32_t& lo)
{
    hi = tf32_rna(x);
    lo = __float_as_uint(x - __uint_as_float(hi));
}

// ---------------------------------------------------------------------------
// Tensor-core 3xTF32 GEMM: out = epilogue( W[M,K] @ X[K,N] ), ~fp32 accuracy.
// CTA tile 128(M) x 128(N); K-chunk 16; 256 threads = 8 warps (2x4).
// Warp tile 64x32; per k-step of 8: Ahi*Bhi + Alo*Bhi + Ahi*Blo.
// MODE 0: X packed,           out = acc*s+b                        (packed)
// MODE 1: X packed + relu-in, out = acc*s+b                        (packed)
// MODE 2: X = x (BCHW, K=256) out = relu(acc*s+b + e0[h] + e1[w])  (packed)
// MODE 3: X = x (BCHW, K=256) out = acc*s+b                        (packed)
// MODE 4: X packed,           out = h_sigmoid(acc*s+b) * e0, scatter to BCHW
// ---------------------------------------------------------------------------
template <int MODE>
__global__ void __launch_bounds__(256, 2)
tc_gemm(const float* __restrict__ Wm,
        const float* __restrict__ X,
        const float* __restrict__ scale,
        const float* __restrict__ bias,
        float* __restrict__ out,
        int K,
        const float* __restrict__ e0,
        const float* __restrict__ e1)
{
    __shared__ float As[16][132];      // [k][m], padded: frag LDS conflict-free
    __shared__ float Bs[16][132];      // [k][n]

    const int t  = threadIdx.x;        // 256
    const int bm = blockIdx.y * 128;
    const int bn = blockIdx.x * 128;
    const int Nld = gridDim.x * 128;

    const int warp = t >> 5, lane = t & 31;
    const int wm = (warp >> 2) * 64;   // 0 | 64
    const int wn = (warp & 3) * 32;    // 0..96
    const int gid = lane >> 2;         // 0..7
    const int tig = lane & 3;          // 0..3

    // gmem load indices
    const int mA = t >> 1;             // 0..127
    const int kq = (t & 1) * 8;        // 0 | 8

    float acc[4][4][4];
    #pragma unroll
    for (int i = 0; i < 4; i++)
        #pragma unroll
        for (int j = 0; j < 4; j++)
            #pragma unroll
            for (int r = 0; r < 4; r++) acc[i][j][r] = 0.f;

    const int NC = K >> 4;
    for (int c = 0; c < NC; c++) {
        const int k0 = c << 4;

        // --- gmem -> regs ---
        const float* wrow = &Wm[(size_t)(bm + mA) * K + k0 + kq];
        float4 av0 = *reinterpret_cast<const float4*>(wrow);
        float4 av1 = *reinterpret_cast<const float4*>(wrow + 4);

        float4 bv[2];
        #pragma unroll
        for (int j = 0; j < 2; j++) {
            const int idx = t + j * 256;
            const int kk = idx >> 5, nf = idx & 31;
            const int kg = k0 + kk;
            float4 v;
            if (MODE == 2 || MODE == 3) {
                const int n = bn + nf * 4;
                const int b = n >> 12, hw = n & 4095;
                v = *reinterpret_cast<const float4*>(
                    &X[((size_t)b * CDIM + kg) * 4096 + hw]);
            } else {
                v = *reinterpret_cast<const float4*>(
                    &X[(size_t)kg * Nld + bn + nf * 4]);
            }
            if (MODE == 1) {
                v.x = fmaxf(v.x, 0.f); v.y = fmaxf(v.y, 0.f);
                v.z = fmaxf(v.z, 0.f); v.w = fmaxf(v.w, 0.f);
            }
            bv[j] = v;
        }

        __syncthreads();               // previous compute done reading smem

        // --- regs -> smem ---
        As[kq + 0][mA] = av0.x; As[kq + 1][mA] = av0.y;
        As[kq + 2][mA] = av0.z; As[kq + 3][mA] = av0.w;
        As[kq + 4][mA] = av1.x; As[kq + 5][mA] = av1.y;
        As[kq + 6][mA] = av1.z; As[kq + 7][mA] = av1.w;
        #pragma unroll
        for (int j = 0; j < 2; j++) {
            const int idx = t + j * 256;
            const int kk = idx >> 5, nf = idx & 31;
            *reinterpret_cast<float4*>(&Bs[kk][nf * 4]) = bv[j];
        }
        __syncthreads();

        // --- compute: 2 k-steps of 8, 3xTF32 per tile ---
        #pragma unroll
        for (int ks = 0; ks < 2; ks++) {
            const int kb = ks * 8;

            // B fragments: hi/lo persist across the mt loop
            uint32_t bhi[4][2], blo[4][2];
            #pragma unroll
            for (int nt = 0; nt < 4; nt++) {
                const int col = wn + nt * 8 + gid;
                tf32_split(Bs[kb + tig][col],     bhi[nt][0], blo[nt][0]);
                tf32_split(Bs[kb + tig + 4][col], bhi[nt][1], blo[nt][1]);
            }

            #pragma unroll
            for (int mt = 0; mt < 4; mt++) {
                const int row = wm + mt * 16 + gid;
                uint32_t ahi[4], alo[4];
                tf32_split(As[kb + tig][row],         ahi[0], alo[0]);
                tf32_split(As[kb + tig][row + 8],     ahi[1], alo[1]);
                tf32_split(As[kb + tig + 4][row],     ahi[2], alo[2]);
                tf32_split(As[kb + tig + 4][row + 8], ahi[3], alo[3]);
                #pragma unroll
                for (int nt = 0; nt < 4; nt++) {
                    mma_tf32(acc[mt][nt], ahi, bhi[nt]);   // hi*hi
                    mma_tf32(acc[mt][nt], alo, bhi[nt]);   // lo*hi
                    mma_tf32(acc[mt][nt], ahi, blo[nt]);   // hi*lo
                }
            }
        }
    }

    // --- epilogue ---
    #pragma unroll
    for (int mt = 0; mt < 4; mt++) {
        const int r0 = bm + wm + mt * 16 + gid;
        const int r1 = r0 + 8;
        const float s0 = scale[r0], bi0 = bias[r0];
        const float s1 = scale[r1], bi1 = bias[r1];
        #pragma unroll
        for (int nt = 0; nt < 4; nt++) {
            const int n0 = bn + wn + nt * 8 + tig * 2;
            float v00 = acc[mt][nt][0] * s0 + bi0;
            float v01 = acc[mt][nt][1] * s0 + bi0;
            float v10 = acc[mt][nt][2] * s1 + bi1;
            float v11 = acc[mt][nt][3] * s1 + bi1;
            if (MODE == 2) {
                const int b = n0 >> 12, hw = n0 & 4095;
                const int h = hw >> 6, w = hw & 63;
                const int o = (b << 6);
                const float re0 = e0[r0 * NAX + o + h];
                const float re1 = e0[r1 * NAX + o + h];
                const float c0a = e1[r0 * NAX + o + w];
                const float c0b = e1[r0 * NAX + o + w + 1];
                const float c1a = e1[r1 * NAX + o + w];
                const float c1b = e1[r1 * NAX + o + w + 1];
                float2 u0, u1;
                u0.x = fmaxf(v00 + re0 + c0a, 0.f);
                u0.y = fmaxf(v01 + re0 + c0b, 0.f);
                u1.x = fmaxf(v10 + re1 + c1a, 0.f);
                u1.y = fmaxf(v11 + re1 + c1b, 0.f);
                *reinterpret_cast<float2*>(&out[(size_t)r0 * Nld + n0]) = u0;
                *reinterpret_cast<float2*>(&out[(size_t)r1 * Nld + n0]) = u1;
            } else if (MODE == 4) {
                const int b = n0 >> 12, hw = n0 & 4095;
                float2 p0 = *reinterpret_cast<const float2*>(&e0[(size_t)r0 * Nld + n0]);
                float2 p1 = *reinterpret_cast<const float2*>(&e0[(size_t)r1 * Nld + n0]);
                float2 u0, u1;
                u0.x = fminf(fmaxf(v00 + 3.f, 0.f), 6.f) * (1.f / 6.f) * p0.x;
                u0.y = fminf(fmaxf(v01 + 3.f, 0.f), 6.f) * (1.f / 6.f) * p0.y;
                u1.x = fminf(fmaxf(v10 + 3.f, 0.f), 6.f) * (1.f / 6.f) * p1.x;
                u1.y = fminf(fmaxf(v11 + 3.f, 0.f), 6.f) * (1.f / 6.f) * p1.y;
                *reinterpret_cast<float2*>(
                    &out[((size_t)b * CDIM + r0) * 4096 + hw]) = u0;
                *reinterpret_cast<float2*>(
                    &out[((size_t)b * CDIM + r1) * 4096 + hw]) = u1;
            } else {
                float2 u0, u1;
                u0.x = v00; u0.y = v01;
                u1.x = v10; u1.y = v11;
                *reinterpret_cast<float2*>(&out[(size_t)r0 * Nld + n0]) = u0;
                *reinterpret_cast<float2*>(&out[(size_t)r1 * Nld + n0]) = u1;
            }
        }
    }
}

// ---------------------------------------------------------------------------
// K1: row/col means of x -> packed [256][2048] (axis 0 = row, axis 1 = col)
// ---------------------------------------------------------------------------
__global__ void mean_kernel(const float* __restrict__ x)
{
    __shared__ float s[64 * 65];
    const int blk = blockIdx.x;                // b*256 + c
    const float* base = x + (size_t)blk * 4096;
    const int t = threadIdx.x;                 // 64 threads

    #pragma unroll
    for (int i = 0; i < 64; i++) s[i * 65 + t] = base[i * 64 + t];
    __syncthreads();

    float rs = 0.f, cs = 0.f;
    #pragma unroll
    for (int i = 0; i < 64; i++) {
        rs += s[t * 65 + i];
        cs += s[i * 65 + t];
    }
    const int b = blk >> 8;
    const int c = blk & 255;
    g_xmean[c * NAX2 + b * 64 + t]        = rs * (1.f / 64.f);
    g_xmean[c * NAX2 + 1024 + b * 64 + t] = cs * (1.f / 64.f);
}

// ---------------------------------------------------------------------------
// K3: axial attention. One block per (axis, b, head); 64 threads.
// ---------------------------------------------------------------------------
__device__ __forceinline__ float pos_interp(const float* __restrict__ p,
                                            int ch, int i)
{
    float c = (i + 0.5f) * 0.25f - 0.5f;
    c = fminf(fmaxf(c, 0.f), 15.f);
    int lo = (int)floorf(c);
    int hi = min(lo + 1, 15);
    float tt = c - (float)lo;
    const float* row = p + ch * 16;
    return row[lo] * (1.f - tt) + row[hi] * tt;
}

__global__ void attn_kernel(const float* __restrict__ pos_rowq,
                            const float* __restrict__ pos_rowk,
                            const float* __restrict__ pos_colq,
                            const float* __restrict__ pos_colk)
{
    const int blk  = blockIdx.x;          // axis*128 + b*8 + head
    const int axis = blk >> 7;
    const int b    = (blk >> 3) & 15;
    const int head = blk & 7;
    const float* pq = axis ? pos_colq : pos_rowq;
    const float* pk = axis ? pos_colk : pos_rowk;
    const int col0 = axis * 1024 + b * 64;

    __shared__ float ks[KEYD][64];
    __shared__ float vs[DV][64];
    const int t = threadIdx.x;            // 64

    float qr[KEYD];
    #pragma unroll
    for (int c = 0; c < KEYD; c++) {
        const int ch = head * KEYD + c;
        ks[c][t] = g_ke[ch * NAX2 + col0 + t] + pos_interp(pk, ch, t);
        qr[c]    = g_qe[ch * NAX2 + col0 + t] + pos_interp(pq, ch, t);
    }
    #pragma unroll
    for (int d = 0; d < DV; d++)
        vs[d][t] = g_ve[(head * DV + d) * NAX2 + col0 + t];
    __syncthreads();

    float S[64];
    float mx = -1e30f;
    #pragma unroll
    for (int j = 0; j < 64; j++) {
        float s = 0.f;
        #pragma unroll
        for (int c = 0; c < KEYD; c++) s += qr[c] * ks[c][j];
        s *= ATTN_SCALE;
        S[j] = s;
        mx = fmaxf(mx, s);
    }
    float sum = 0.f;
    #pragma unroll
    for (int j = 0; j < 64; j++) { S[j] = __expf(S[j] - mx); sum += S[j]; }
    const float inv = 1.f / sum;

    float* xo = g_xx[axis];
    #pragma unroll
    for (int d = 0; d < DV; d++) {
        float o = 0.f;
        #pragma unroll
        for (int j = 0; j < 64; j++) o += S[j] * vs[d][j];
        xo[(head * DV + d) * NAX + b * 64 + t] = o * inv;
    }
}

// ---------------------------------------------------------------------------
// K6b: depthwise 3x3 (SAME, zero pad) + affine + relu.  g1 -> g2
// ---------------------------------------------------------------------------
__global__ void dw_kernel(const float* __restrict__ wdw,
                          const float* __restrict__ sdw,
                          const float* __restrict__ bdw)
{
    const long long idx = (long long)blockIdx.x * blockDim.x + threadIdx.x;
    if (idx >= (long long)CDIM * NPIX) return;
    const int n = (int)(idx & (NPIX - 1));
    const int c = (int)(idx >> 16);
    const int b = n >> 12, hw = n & 4095;
    const int h = hw >> 6, w = hw & 63;
    const float* base = g_g1 + (size_t)c * NPIX + (size_t)b * 4096;
    const float* wk = wdw + c * 9;

    float acc = 0.f;
    #pragma unroll
    for (int dy = 0; dy < 3; dy++) {
        const int hh = h + dy - 1;
        if (hh < 0 || hh > 63) continue;
        #pragma unroll
        for (int dx = 0; dx < 3; dx++) {
            const int ww = w + dx - 1;
            if (ww < 0 || ww > 63) continue;
            acc += base[hh * 64 + ww] * wk[dy * 3 + dx];
        }
    }
    float v = acc * sdw[c] + bdw[c];
    g_g2[idx] = fmaxf(v, 0.f);
}

// ---------------------------------------------------------------------------
// Host launcher
// ---------------------------------------------------------------------------
extern "C" void kernel_launch(void* const* d_in, const int* in_sizes, int n_in,
                              void* d_out, int out_size)
{
    const float* x        = (const float*)d_in[0];
    const float* wq       = (const float*)d_in[1];
    const float* sq       = (const float*)d_in[2];
    const float* bq       = (const float*)d_in[3];
    const float* wk       = (const float*)d_in[4];
    const float* sk       = (const float*)d_in[5];
    const float* bk       = (const float*)d_in[6];
    const float* wv       = (const float*)d_in[7];
    const float* sv       = (const float*)d_in[8];
    const float* bv       = (const float*)d_in[9];
    const float* pos_rowq = (const float*)d_in[10];
    const float* pos_rowk = (const float*)d_in[11];
    const float* pos_colq = (const float*)d_in[12];
    const float* pos_colk = (const float*)d_in[13];
    const float* w_row    = (const float*)d_in[14];
    const float* s_row    = (const float*)d_in[15];
    const float* b_row    = (const float*)d_in[16];
    const float* w_col    = (const float*)d_in[17];
    const float* s_col    = (const float*)d_in[18];
    const float* b_col    = (const float*)d_in[19];
    const float* w_proj   = (const float*)d_in[20];
    const float* s_proj   = (const float*)d_in[21];
    const float* b_proj   = (const float*)d_in[22];
    const float* w_sc     = (const float*)d_in[23];
    const float* s_sc     = (const float*)d_in[24];
    const float* b_sc     = (const float*)d_in[25];
    const float* w_dw     = (const float*)d_in[26];
    const float* s_dw     = (const float*)d_in[27];
    const float* b_dw     = (const float*)d_in[28];
    const float* w_pw     = (const float*)d_in[29];
    const float* s_pw     = (const float*)d_in[30];
    const float* b_pw     = (const float*)d_in[31];

    float *p_xm, *p_qe, *p_ke, *p_ve, *p_xx, *p_rout, *p_A, *p_g1, *p_g2, *p_P;
    cudaGetSymbolAddress((void**)&p_xm,   g_xmean);
    cudaGetSymbolAddress((void**)&p_qe,   g_qe);
    cudaGetSymbolAddress((void**)&p_ke,   g_ke);
    cudaGetSymbolAddress((void**)&p_ve,   g_ve);
    cudaGetSymbolAddress((void**)&p_xx,   g_xx);
    cudaGetSymbolAddress((void**)&p_rout, g_rout);
    cudaGetSymbolAddress((void**)&p_A,    g_A);
    cudaGetSymbolAddress((void**)&p_g1,   g_g1);
    cudaGetSymbolAddress((void**)&p_g2,   g_g2);
    cudaGetSymbolAddress((void**)&p_P,    g_P);

    // K1: means (both axes into one [256][2048] buffer)
    mean_kernel<<<BB * CDIM, 64>>>(x);

    // K2: q/k/v projections on mean vectors (both axes at once, N=2048)
    tc_gemm<0><<<dim3(NAX2 / 128, NHKD / 128), 256>>>(
        wq, p_xm, sq, bq, p_qe, CDIM, nullptr, nullptr);
    tc_gemm<0><<<dim3(NAX2 / 128, NHKD / 128), 256>>>(
        wk, p_xm, sk, bk, p_ke, CDIM, nullptr, nullptr);
    tc_gemm<0><<<dim3(NAX2 / 128, DHD / 128), 256>>>(
        wv, p_xm, sv, bv, p_ve, CDIM, nullptr, nullptr);

    // K3: axial attention (both axes)
    attn_kernel<<<2 * BB * NHEADS, 64>>>(pos_rowq, pos_rowk, pos_colq, pos_colk);

    // K4: w_row / w_col cbn on relu(xx)
    tc_gemm<1><<<dim3(NAX / 128, DHD / 128), 256>>>(
        w_row, p_xx, s_row, b_row, p_rout, DHD, nullptr, nullptr);
    tc_gemm<1><<<dim3(NAX / 128, DHD / 128), 256>>>(
        w_col, p_xx + (size_t)DHD * NAX, s_col, b_col,
        p_rout + (size_t)DHD * NAX, DHD, nullptr, nullptr);

    // K5: A = relu(v + row + col)   (big GEMM over all pixels)
    tc_gemm<2><<<dim3(NPIX / 128, DHD / 128), 256>>>(
        wv, x, sv, bv, p_A, CDIM, p_rout, p_rout + (size_t)DHD * NAX);

    // K5g: g1 = cbn(x, w_sc)
    tc_gemm<3><<<dim3(NPIX / 128, CDIM / 128), 256>>>(
        w_sc, x, s_sc, b_sc, p_g1, CDIM, nullptr, nullptr);

    // K6a: P = cbn(A, w_proj)
    tc_gemm<0><<<dim3(NPIX / 128, CDIM / 128), 256>>>(
        w_proj, p_A, s_proj, b_proj, p_P, DHD, nullptr, nullptr);

    // K6b: depthwise 3x3 + affine + relu
    dw_kernel<<<(CDIM * NPIX) / 256, 256>>>(w_dw, s_dw, b_dw);

    // K6c: out = h_sigmoid(cbn(g2, w_pw)) * P  (scatter to NCHW)
    tc_gemm<4><<<dim3(NPIX / 128, CDIM / 128), 256>>>(
        w_pw, p_g2, s_pw, b_pw, (float*)d_out, CDIM, p_P, nullptr);
}

// round 12
// speedup vs baseline: 2.5345x; 1.2375x over previous
#include <cuda_runtime.h>
#include <cstdint>
#include <cstddef>

// ---------------------------------------------------------------------------
// Problem constants
// ---------------------------------------------------------------------------
#define BB     16
#define CDIM   256
#define HDIM   64
#define WDIM   64
#define NHKD   128
#define DHD    512
#define NPIX   65536        // BB*HDIM*WDIM
#define NAX    1024         // BB*64
#define NAX2   2048         // both axes packed
#define NHEADS 8
#define KEYD   16
#define DV     64
#define ATTN_SCALE 0.25f

#define A_STRIDE 20         // floats per A smem row (16 data + 4 pad)
#define B_STRIDE 136        // floats per B smem row (128 data + 8 pad)
#define A_STAGE  (128 * A_STRIDE)
#define B_STAGE  (16 * B_STRIDE)

// ---------------------------------------------------------------------------
// Scratch (device globals; no allocation allowed)
// ---------------------------------------------------------------------------
__device__ float g_xmean[CDIM * NAX2];         // [c][axis*1024 + b*64 + p]
__device__ float g_qe[NHKD * NAX2];
__device__ float g_ke[NHKD * NAX2];
__device__ float g_ve[DHD * NAX2];
__device__ float g_xx[2][DHD * NAX];           // attention output (pre-relu)
__device__ float g_rout[2][DHD * NAX];         // after w_row / w_col cbn
__device__ float g_A[(size_t)DHD * NPIX];      // relu(v + row + col), packed [m][n]
__device__ float g_g1[(size_t)CDIM * NPIX];    // gate after w_sc cbn, packed [c][n]
__device__ float g_g2[(size_t)CDIM * NPIX];    // relu(dw(g1)), packed [c][n]
__device__ float g_P[(size_t)CDIM * NPIX];     // proj output, packed [m][n]

// ---------------------------------------------------------------------------
// PTX helpers
// ---------------------------------------------------------------------------
__device__ __forceinline__ void mma_tf32(float* c, const uint32_t* a,
                                         const uint32_t* b)
{
    asm volatile(
        "mma.sync.aligned.m16n8k8.row.col.f32.tf32.tf32.f32 "
        "{%0,%1,%2,%3}, {%4,%5,%6,%7}, {%8,%9}, {%0,%1,%2,%3};"
        : "+f"(c[0]), "+f"(c[1]), "+f"(c[2]), "+f"(c[3])
        : "r"(a[0]), "r"(a[1]), "r"(a[2]), "r"(a[3]),
          "r"(b[0]), "r"(b[1]));
}

__device__ __forceinline__ uint32_t tf32_rna(float x)
{
    uint32_t r;
    asm("cvt.rna.tf32.f32 %0, %1;" : "=r"(r) : "f"(x));
    return r;
}

__device__ __forceinline__ void tf32_split(float x, uint32_t& hi, uint32_t& lo)
{
    hi = tf32_rna(x);
    lo = __float_as_uint(x - __uint_as_float(hi));
}

__device__ __forceinline__ void cp16(void* dst_smem, const void* src)
{
    uint32_t d = (uint32_t)__cvta_generic_to_shared(dst_smem);
    asm volatile("cp.async.cg.shared.global [%0], [%1], 16;"
                 :: "r"(d), "l"(src));
}
#define CP_COMMIT() asm volatile("cp.async.commit_group;" ::: "memory")
#define CP_WAIT1()  asm volatile("cp.async.wait_group 1;" ::: "memory")

// ---------------------------------------------------------------------------
// 3xTF32 GEMM core: out = epilogue( W[M,K] @ X[K,N] ), ~fp32 accuracy.
// CTA tile 128(M) x 128(N); K-chunk 16; cp.async 2-stage double buffer.
// 256 threads = 8 warps (2x4); warp tile 64x32.
// Per k-step of 8: Ahi*Bhi + Alo*Bhi + Ahi*Blo.
// MODE 0: X packed,           out = acc*s+b                        (packed)
// MODE 1: X packed + relu-in, out = acc*s+b                        (packed)
// MODE 2: X = x (BCHW, K=256) out = relu(acc*s+b + e0[h] + e1[w])  (packed)
// MODE 3: X = x (BCHW, K=256) out = acc*s+b                        (packed)
// MODE 4: X packed,           out = h_sigmoid(acc*s+b) * e0, scatter to BCHW
// ---------------------------------------------------------------------------
template <int MODE>
__device__ __forceinline__ void gemm_core(
    const float* __restrict__ Wm, const float* __restrict__ X,
    const float* __restrict__ scale, const float* __restrict__ bias,
    float* __restrict__ out, int K,
    const float* __restrict__ e0, const float* __restrict__ e1,
    int bm, int bn, int Nld, float* As, float* Bs)
{
    const int t = threadIdx.x;         // 256
    const int warp = t >> 5, lane = t & 31;
    const int wm = (warp >> 2) * 64;   // 0 | 64
    const int wn = (warp & 3) * 32;    // 0..96
    const int gid = lane >> 2;         // 0..7
    const int tig = lane & 3;          // 0..3

    const int mA = t >> 1;             // 0..127
    const int kq = (t & 1) * 8;        // 0 | 8

    float acc[4][4][4];
    #pragma unroll
    for (int i = 0; i < 4; i++)
        #pragma unroll
        for (int j = 0; j < 4; j++)
            #pragma unroll
            for (int r = 0; r < 4; r++) acc[i][j][r] = 0.f;

    const int NC = K >> 4;

    // stage issue: chunk c -> buffer c&1
    auto issue = [&](int c) {
        const int st = c & 1;
        const int k0 = c << 4;
        const float* wsrc = &Wm[(size_t)(bm + mA) * K + k0 + kq];
        float* ad = As + st * A_STAGE + mA * A_STRIDE + kq;
        cp16(ad, wsrc);
        cp16(ad + 4, wsrc + 4);
        #pragma unroll
        for (int j = 0; j < 2; j++) {
            const int idx = t + j * 256;
            const int kk = idx >> 5, nf = idx & 31;
            const int kg = k0 + kk;
            const float* src;
            if (MODE == 2 || MODE == 3) {
                const int n = bn + nf * 4;
                const int b = n >> 12, hw = n & 4095;
                src = &X[((size_t)b * CDIM + kg) * 4096 + hw];
            } else {
                src = &X[(size_t)kg * Nld + bn + nf * 4];
            }
            cp16(Bs + st * B_STAGE + kk * B_STRIDE + nf * 4, src);
        }
    };

    issue(0);
    CP_COMMIT();

    for (int c = 0; c < NC; c++) {
        if (c + 1 < NC) issue(c + 1);
        CP_COMMIT();
        CP_WAIT1();                    // chunk c landed
        __syncthreads();

        const int st = c & 1;
        const float* Ab = As + st * A_STAGE;
        const float* Bb = Bs + st * B_STAGE;

        #pragma unroll
        for (int ks = 0; ks < 2; ks++) {
            const int kb = ks * 8;

            uint32_t bhi[4][2], blo[4][2];
            #pragma unroll
            for (int nt = 0; nt < 4; nt++) {
                const int col = wn + nt * 8 + gid;
                float b0 = Bb[(kb + tig) * B_STRIDE + col];
                float b1 = Bb[(kb + tig + 4) * B_STRIDE + col];
                if (MODE == 1) { b0 = fmaxf(b0, 0.f); b1 = fmaxf(b1, 0.f); }
                tf32_split(b0, bhi[nt][0], blo[nt][0]);
                tf32_split(b1, bhi[nt][1], blo[nt][1]);
            }

            #pragma unroll
            for (int mt = 0; mt < 4; mt++) {
                const int row = wm + mt * 16 + gid;
                uint32_t ahi[4], alo[4];
                tf32_split(Ab[row * A_STRIDE + kb + tig],           ahi[0], alo[0]);
                tf32_split(Ab[(row + 8) * A_STRIDE + kb + tig],     ahi[1], alo[1]);
                tf32_split(Ab[row * A_STRIDE + kb + tig + 4],       ahi[2], alo[2]);
                tf32_split(Ab[(row + 8) * A_STRIDE + kb + tig + 4], ahi[3], alo[3]);
                #pragma unroll
                for (int nt = 0; nt < 4; nt++) {
                    mma_tf32(acc[mt][nt], ahi, bhi[nt]);   // hi*hi
                    mma_tf32(acc[mt][nt], alo, bhi[nt]);   // lo*hi
                    mma_tf32(acc[mt][nt], ahi, blo[nt]);   // hi*lo
                }
            }
        }
        __syncthreads();               // done reading stage before overwrite
    }

    // --- epilogue ---
    #pragma unroll
    for (int mt = 0; mt < 4; mt++) {
        const int r0 = bm + wm + mt * 16 + gid;
        const int r1 = r0 + 8;
        const float s0 = scale[r0], bi0 = bias[r0];
        const float s1 = scale[r1], bi1 = bias[r1];
        #pragma unroll
        for (int nt = 0; nt < 4; nt++) {
            const int n0 = bn + wn + nt * 8 + tig * 2;
            float v00 = acc[mt][nt][0] * s0 + bi0;
            float v01 = acc[mt][nt][1] * s0 + bi0;
            float v10 = acc[mt][nt][2] * s1 + bi1;
            float v11 = acc[mt][nt][3] * s1 + bi1;
            if (MODE == 2) {
                const int b = n0 >> 12, hw = n0 & 4095;
                const int h = hw >> 6, w = hw & 63;
                const int o = (b << 6);
                const float re0 = e0[r0 * NAX + o + h];
                const float re1 = e0[r1 * NAX + o + h];
                const float c0a = e1[r0 * NAX + o + w];
                const float c0b = e1[r0 * NAX + o + w + 1];
                const float c1a = e1[r1 * NAX + o + w];
                const float c1b = e1[r1 * NAX + o + w + 1];
                float2 u0, u1;
                u0.x = fmaxf(v00 + re0 + c0a, 0.f);
                u0.y = fmaxf(v01 + re0 + c0b, 0.f);
                u1.x = fmaxf(v10 + re1 + c1a, 0.f);
                u1.y = fmaxf(v11 + re1 + c1b, 0.f);
                *reinterpret_cast<float2*>(&out[(size_t)r0 * Nld + n0]) = u0;
                *reinterpret_cast<float2*>(&out[(size_t)r1 * Nld + n0]) = u1;
            } else if (MODE == 4) {
                const int b = n0 >> 12, hw = n0 & 4095;
                float2 p0 = *reinterpret_cast<const float2*>(&e0[(size_t)r0 * Nld + n0]);
                float2 p1 = *reinterpret_cast<const float2*>(&e0[(size_t)r1 * Nld + n0]);
                float2 u0, u1;
                u0.x = fminf(fmaxf(v00 + 3.f, 0.f), 6.f) * (1.f / 6.f) * p0.x;
                u0.y = fminf(fmaxf(v01 + 3.f, 0.f), 6.f) * (1.f / 6.f) * p0.y;
                u1.x = fminf(fmaxf(v10 + 3.f, 0.f), 6.f) * (1.f / 6.f) * p1.x;
                u1.y = fminf(fmaxf(v11 + 3.f, 0.f), 6.f) * (1.f / 6.f) * p1.y;
                *reinterpret_cast<float2*>(
                    &out[((size_t)b * CDIM + r0) * 4096 + hw]) = u0;
                *reinterpret_cast<float2*>(
                    &out[((size_t)b * CDIM + r1) * 4096 + hw]) = u1;
            } else {
                float2 u0, u1;
                u0.x = v00; u0.y = v01;
                u1.x = v10; u1.y = v11;
                *reinterpret_cast<float2*>(&out[(size_t)r0 * Nld + n0]) = u0;
                *reinterpret_cast<float2*>(&out[(size_t)r1 * Nld + n0]) = u1;
            }
        }
    }
}

// ---------------------------------------------------------------------------
// GEMM kernel wrappers
// ---------------------------------------------------------------------------
template <int MODE>
__global__ void __launch_bounds__(256, 2)
tc_gemm(const float* __restrict__ Wm, const float* __restrict__ X,
        const float* __restrict__ scale, const float* __restrict__ bias,
        float* __restrict__ out, int K,
        const float* __restrict__ e0, const float* __restrict__ e1)
{
    __shared__ float As[2 * A_STAGE];
    __shared__ float Bs[2 * B_STAGE];
    gemm_core<MODE>(Wm, X, scale, bias, out, K, e0, e1,
                    blockIdx.y * 128, blockIdx.x * 128, gridDim.x * 128,
                    As, Bs);
}

// batched q/k/v projection: z=0 -> q (M=128), z=1 -> k (M=128), z=2 -> v (M=512)
__global__ void __launch_bounds__(256, 2)
tc_gemm_qkv(const float* __restrict__ wq, const float* __restrict__ sq,
            const float* __restrict__ bq, float* __restrict__ oq,
            const float* __restrict__ wk, const float* __restrict__ sk,
            const float* __restrict__ bk, float* __restrict__ ok,
            const float* __restrict__ wv, const float* __restrict__ sv,
            const float* __restrict__ bv, float* __restrict__ ov,
            const float* __restrict__ X)
{
    __shared__ float As[2 * A_STAGE];
    __shared__ float Bs[2 * B_STAGE];
    const int z = blockIdx.z;
    const int yv = (z < 2) ? 1 : 4;
    if ((int)blockIdx.y >= yv) return;
    const float* W = (z == 0) ? wq : (z == 1) ? wk : wv;
    const float* s = (z == 0) ? sq : (z == 1) ? sk : sv;
    const float* b = (z == 0) ? bq : (z == 1) ? bk : bv;
    float*       o = (z == 0) ? oq : (z == 1) ? ok : ov;
    gemm_core<0>(W, X, s, b, o, CDIM, nullptr, nullptr,
                 blockIdx.y * 128, blockIdx.x * 128, NAX2, As, Bs);
}

// batched row/col cbn: z selects weight set + xx/rout slab
__global__ void __launch_bounds__(256, 2)
tc_gemm_rowcol(const float* __restrict__ w_row, const float* __restrict__ s_row,
               const float* __restrict__ b_row,
               const float* __restrict__ w_col, const float* __restrict__ s_col,
               const float* __restrict__ b_col,
               const float* __restrict__ xx, float* __restrict__ rout)
{
    __shared__ float As[2 * A_STAGE];
    __shared__ float Bs[2 * B_STAGE];
    const int z = blockIdx.z;
    const float* W = z ? w_col : w_row;
    const float* s = z ? s_col : s_row;
    const float* b = z ? b_col : b_row;
    const float* X = xx + (size_t)z * DHD * NAX;
    float*       o = rout + (size_t)z * DHD * NAX;
    gemm_core<1>(W, X, s, b, o, DHD, nullptr, nullptr,
                 blockIdx.y * 128, blockIdx.x * 128, NAX, As, Bs);
}

// ---------------------------------------------------------------------------
// K1: row/col means of x -> packed [256][2048] (axis 0 = row, axis 1 = col)
// ---------------------------------------------------------------------------
__global__ void mean_kernel(const float* __restrict__ x)
{
    __shared__ float s[64 * 65];
    const int blk = blockIdx.x;                // b*256 + c
    const float* base = x + (size_t)blk * 4096;
    const int t = threadIdx.x;                 // 64 threads

    #pragma unroll
    for (int i = 0; i < 64; i++) s[i * 65 + t] = base[i * 64 + t];
    __syncthreads();

    float rs = 0.f, cs = 0.f;
    #pragma unroll
    for (int i = 0; i < 64; i++) {
        rs += s[t * 65 + i];
        cs += s[i * 65 + t];
    }
    const int b = blk >> 8;
    const int c = blk & 255;
    g_xmean[c * NAX2 + b * 64 + t]        = rs * (1.f / 64.f);
    g_xmean[c * NAX2 + 1024 + b * 64 + t] = cs * (1.f / 64.f);
}

// ---------------------------------------------------------------------------
// K3: axial attention. One block per (axis, b, head); 64 threads.
// ---------------------------------------------------------------------------
__device__ __forceinline__ float pos_interp(const float* __restrict__ p,
                                            int ch, int i)
{
    float c = (i + 0.5f) * 0.25f - 0.5f;
    c = fminf(fmaxf(c, 0.f), 15.f);
    int lo = (int)floorf(c);
    int hi = min(lo + 1, 15);
    float tt = c - (float)lo;
    const float* row = p + ch * 16;
    return row[lo] * (1.f - tt) + row[hi] * tt;
}

__global__ void attn_kernel(const float* __restrict__ pos_rowq,
                            const float* __restrict__ pos_rowk,
                            const float* __restrict__ pos_colq,
                            const float* __restrict__ pos_colk)
{
    const int blk  = blockIdx.x;          // axis*128 + b*8 + head
    const int axis = blk >> 7;
    const int b    = (blk >> 3) & 15;
    const int head = blk & 7;
    const float* pq = axis ? pos_colq : pos_rowq;
    const float* pk = axis ? pos_colk : pos_rowk;
    const int col0 = axis * 1024 + b * 64;

    __shared__ float ks[KEYD][64];
    __shared__ float vs[DV][64];
    const int t = threadIdx.x;            // 64

    float qr[KEYD];
    #pragma unroll
    for (int c = 0; c < KEYD; c++) {
        const int ch = head * KEYD + c;
        ks[c][t] = g_ke[ch * NAX2 + col0 + t] + pos_interp(pk, ch, t);
        qr[c]    = g_qe[ch * NAX2 + col0 + t] + pos_interp(pq, ch, t);
    }
    #pragma unroll
    for (int d = 0; d < DV; d++)
        vs[d][t] = g_ve[(head * DV + d) * NAX2 + col0 + t];
    __syncthreads();

    float S[64];
    float mx = -1e30f;
    #pragma unroll
    for (int j = 0; j < 64; j++) {
        float s = 0.f;
        #pragma unroll
        for (int c = 0; c < KEYD; c++) s += qr[c] * ks[c][j];
        s *= ATTN_SCALE;
        S[j] = s;
        mx = fmaxf(mx, s);
    }
    float sum = 0.f;
    #pragma unroll
    for (int j = 0; j < 64; j++) { S[j] = __expf(S[j] - mx); sum += S[j]; }
    const float inv = 1.f / sum;

    float* xo = g_xx[axis];
    #pragma unroll
    for (int d = 0; d < DV; d++) {
        float o = 0.f;
        #pragma unroll
        for (int j = 0; j < 64; j++) o += S[j] * vs[d][j];
        xo[(head * DV + d) * NAX + b * 64 + t] = o * inv;
    }
}

// ---------------------------------------------------------------------------
// K6b: depthwise 3x3 (SAME, zero pad) + affine + relu.  g1 -> g2
// ---------------------------------------------------------------------------
__global__ void dw_kernel(const float* __restrict__ wdw,
                          const float* __restrict__ sdw,
                          const float* __restrict__ bdw)
{
    const long long idx = (long long)blockIdx.x * blockDim.x + threadIdx.x;
    if (idx >= (long long)CDIM * NPIX) return;
    const int n = (int)(idx & (NPIX - 1));
    const int c = (int)(idx >> 16);
    const int b = n >> 12, hw = n & 4095;
    const int h = hw >> 6, w = hw & 63;
    const float* base = g_g1 + (size_t)c * NPIX + (size_t)b * 4096;
    const float* wk = wdw + c * 9;

    float acc = 0.f;
    #pragma unroll
    for (int dy = 0; dy < 3; dy++) {
        const int hh = h + dy - 1;
        if (hh < 0 || hh > 63) continue;
        #pragma unroll
        for (int dx = 0; dx < 3; dx++) {
            const int ww = w + dx - 1;
            if (ww < 0 || ww > 63) continue;
            acc += base[hh * 64 + ww] * wk[dy * 3 + dx];
        }
    }
    float v = acc * sdw[c] + bdw[c];
    g_g2[idx] = fmaxf(v, 0.f);
}

// ---------------------------------------------------------------------------
// Host launcher
// ---------------------------------------------------------------------------
extern "C" void kernel_launch(void* const* d_in, const int* in_sizes, int n_in,
                              void* d_out, int out_size)
{
    const float* x        = (const float*)d_in[0];
    const float* wq       = (const float*)d_in[1];
    const float* sq       = (const float*)d_in[2];
    const float* bq       = (const float*)d_in[3];
    const float* wk       = (const float*)d_in[4];
    const float* sk       = (const float*)d_in[5];
    const float* bk       = (const float*)d_in[6];
    const float* wv       = (const float*)d_in[7];
    const float* sv       = (const float*)d_in[8];
    const float* bv       = (const float*)d_in[9];
    const float* pos_rowq = (const float*)d_in[10];
    const float* pos_rowk = (const float*)d_in[11];
    const float* pos_colq = (const float*)d_in[12];
    const float* pos_colk = (const float*)d_in[13];
    const float* w_row    = (const float*)d_in[14];
    const float* s_row    = (const float*)d_in[15];
    const float* b_row    = (const float*)d_in[16];
    const float* w_col    = (const float*)d_in[17];
    const float* s_col    = (const float*)d_in[18];
    const float* b_col    = (const float*)d_in[19];
    const float* w_proj   = (const float*)d_in[20];
    const float* s_proj   = (const float*)d_in[21];
    const float* b_proj   = (const float*)d_in[22];
    const float* w_sc     = (const float*)d_in[23];
    const float* s_sc     = (const float*)d_in[24];
    const float* b_sc     = (const float*)d_in[25];
    const float* w_dw     = (const float*)d_in[26];
    const float* s_dw     = (const float*)d_in[27];
    const float* b_dw     = (const float*)d_in[28];
    const float* w_pw     = (const float*)d_in[29];
    const float* s_pw     = (const float*)d_in[30];
    const float* b_pw     = (const float*)d_in[31];

    float *p_xm, *p_qe, *p_ke, *p_ve, *p_xx, *p_rout, *p_A, *p_g1, *p_g2, *p_P;
    cudaGetSymbolAddress((void**)&p_xm,   g_xmean);
    cudaGetSymbolAddress((void**)&p_qe,   g_qe);
    cudaGetSymbolAddress((void**)&p_ke,   g_ke);
    cudaGetSymbolAddress((void**)&p_ve,   g_ve);
    cudaGetSymbolAddress((void**)&p_xx,   g_xx);
    cudaGetSymbolAddress((void**)&p_rout, g_rout);
    cudaGetSymbolAddress((void**)&p_A,    g_A);
    cudaGetSymbolAddress((void**)&p_g1,   g_g1);
    cudaGetSymbolAddress((void**)&p_g2,   g_g2);
    cudaGetSymbolAddress((void**)&p_P,    g_P);

    // K1: means (both axes into one [256][2048] buffer)
    mean_kernel<<<BB * CDIM, 64>>>(x);

    // K2: q/k/v projections, single batched launch (z = q,k,v)
    tc_gemm_qkv<<<dim3(NAX2 / 128, 4, 3), 256>>>(
        wq, sq, bq, p_qe, wk, sk, bk, p_ke, wv, sv, bv, p_ve, p_xm);

    // K3: axial attention (both axes)
    attn_kernel<<<2 * BB * NHEADS, 64>>>(pos_rowq, pos_rowk, pos_colq, pos_colk);

    // K4: w_row / w_col cbn on relu(xx), single batched launch
    tc_gemm_rowcol<<<dim3(NAX / 128, DHD / 128, 2), 256>>>(
        w_row, s_row, b_row, w_col, s_col, b_col, p_xx, p_rout);

    // K5: A = relu(v + row + col)   (big GEMM over all pixels)
    tc_gemm<2><<<dim3(NPIX / 128, DHD / 128), 256>>>(
        wv, x, sv, bv, p_A, CDIM, p_rout, p_rout + (size_t)DHD * NAX);

    // K5g: g1 = cbn(x, w_sc)
    tc_gemm<3><<<dim3(NPIX / 128, CDIM / 128), 256>>>(
        w_sc, x, s_sc, b_sc, p_g1, CDIM, nullptr, nullptr);

    // K6a: P = cbn(A, w_proj)
    tc_gemm<0><<<dim3(NPIX / 128, CDIM / 128), 256>>>(
        w_proj, p_A, s_proj, b_proj, p_P, DHD, nullptr, nullptr);

    // K6b: depthwise 3x3 + affine + relu
    dw_kernel<<<(CDIM * NPIX) / 256, 256>>>(w_dw, s_dw, b_dw);

    // K6c: out = h_sigmoid(cbn(g2, w_pw)) * P  (scatter to NCHW)
    tc_gemm<4><<<dim3(NPIX / 128, CDIM / 128), 256>>>(
        w_pw, p_g2, s_pw, b_pw, (float*)d_out, CDIM, p_P, nullptr);
}

// round 13
// speedup vs baseline: 2.5600x; 1.0100x over previous
#include <cuda_runtime.h>
#include <cstdint>
#include <cstddef>

// ---------------------------------------------------------------------------
// Problem constants
// ---------------------------------------------------------------------------
#define BB     16
#define CDIM   256
#define HDIM   64
#define WDIM   64
#define NHKD   128
#define DHD    512
#define NPIX   65536        // BB*HDIM*WDIM
#define NAX    1024         // BB*64
#define NAX2   2048         // both axes packed
#define NHEADS 8
#define KEYD   16
#define DV     64
#define ATTN_SCALE 0.25f

#define A_STRIDE 20         // floats per A smem row (16 data + 4 pad)
#define B_STRIDE 136        // floats per B smem row (128 data + 8 pad)
#define A_STAGE  (128 * A_STRIDE)
#define B_STAGE  (16 * B_STRIDE)
#define NSTAGE   3
#define SMEM_SZ  (NSTAGE * (A_STAGE + B_STAGE) * 4)   // 56832 bytes

// ---------------------------------------------------------------------------
// Scratch (device globals; no allocation allowed)
// ---------------------------------------------------------------------------
__device__ float g_xmean[CDIM * NAX2];         // [c][axis*1024 + b*64 + p]
__device__ float g_qe[NHKD * NAX2];
__device__ float g_ke[NHKD * NAX2];
__device__ float g_ve[DHD * NAX2];
__device__ float g_xx[2][DHD * NAX];           // attention output (pre-relu)
__device__ float g_rout[2][DHD * NAX];         // after w_row / w_col cbn
__device__ float g_A[(size_t)DHD * NPIX];      // relu(v + row + col), packed [m][n]
__device__ float g_g1[(size_t)CDIM * NPIX];    // gate after w_sc cbn, packed [c][n]
__device__ float g_g2[(size_t)CDIM * NPIX];    // relu(dw(g1)), packed [c][n]
__device__ float g_P[(size_t)CDIM * NPIX];     // proj output, packed [m][n]

// ---------------------------------------------------------------------------
// PTX helpers
// ---------------------------------------------------------------------------
__device__ __forceinline__ void mma_tf32(float* c, const uint32_t* a,
                                         const uint32_t* b)
{
    asm volatile(
        "mma.sync.aligned.m16n8k8.row.col.f32.tf32.tf32.f32 "
        "{%0,%1,%2,%3}, {%4,%5,%6,%7}, {%8,%9}, {%0,%1,%2,%3};"
        : "+f"(c[0]), "+f"(c[1]), "+f"(c[2]), "+f"(c[3])
        : "r"(a[0]), "r"(a[1]), "r"(a[2]), "r"(a[3]),
          "r"(b[0]), "r"(b[1]));
}

__device__ __forceinline__ uint32_t tf32_rna(float x)
{
    uint32_t r;
    asm("cvt.rna.tf32.f32 %0, %1;" : "=r"(r) : "f"(x));
    return r;
}

__device__ __forceinline__ void tf32_split(float x, uint32_t& hi, uint32_t& lo)
{
    hi = tf32_rna(x);
    lo = __float_as_uint(x - __uint_as_float(hi));
}

__device__ __forceinline__ void cp16(void* dst_smem, const void* src)
{
    uint32_t d = (uint32_t)__cvta_generic_to_shared(dst_smem);
    asm volatile("cp.async.cg.shared.global [%0], [%1], 16;"
                 :: "r"(d), "l"(src));
}
#define CP_COMMIT() asm volatile("cp.async.commit_group;" ::: "memory")
#define CP_WAIT2()  asm volatile("cp.async.wait_group 2;" ::: "memory")

// ---------------------------------------------------------------------------
// 3xTF32 GEMM core: out = epilogue( W[M,K] @ X[K,N] ), ~fp32 accuracy.
// CTA tile 128(M) x 128(N); K-chunk 16; cp.async 3-stage pipeline.
// 256 threads = 8 warps (2x4); warp tile 64x32.
// Pass-major MMA order over mt-pairs: dependent accumulator reuses are
// separated by 8 independent MMAs (hides HMMA latency).
// MODE 0: X packed,           out = acc*s+b                        (packed)
// MODE 1: X packed + relu-in, out = acc*s+b                        (packed)
// MODE 2: X = x (BCHW, K=256) out = relu(acc*s+b + e0[h] + e1[w])  (packed)
// MODE 3: X = x (BCHW, K=256) out = acc*s+b                        (packed)
// MODE 4: X packed,           out = h_sigmoid(acc*s+b) * e0, scatter to BCHW
// ---------------------------------------------------------------------------
template <int MODE>
__device__ __forceinline__ void gemm_core(
    const float* __restrict__ Wm, const float* __restrict__ X,
    const float* __restrict__ scale, const float* __restrict__ bias,
    float* __restrict__ out, int K,
    const float* __restrict__ e0, const float* __restrict__ e1,
    int bm, int bn, int Nld, float* As, float* Bs)
{
    const int t = threadIdx.x;         // 256
    const int warp = t >> 5, lane = t & 31;
    const int wm = (warp >> 2) * 64;   // 0 | 64
    const int wn = (warp & 3) * 32;    // 0..96
    const int gid = lane >> 2;         // 0..7
    const int tig = lane & 3;          // 0..3

    const int mA = t >> 1;             // 0..127
    const int kq = (t & 1) * 8;        // 0 | 8

    float acc[4][4][4];
    #pragma unroll
    for (int i = 0; i < 4; i++)
        #pragma unroll
        for (int j = 0; j < 4; j++)
            #pragma unroll
            for (int r = 0; r < 4; r++) acc[i][j][r] = 0.f;

    const int NC = K >> 4;

    // stage issue: chunk c -> buffer c % NSTAGE
    auto issue = [&](int c) {
        const int st = c % NSTAGE;
        const int k0 = c << 4;
        const float* wsrc = &Wm[(size_t)(bm + mA) * K + k0 + kq];
        float* ad = As + st * A_STAGE + mA * A_STRIDE + kq;
        cp16(ad, wsrc);
        cp16(ad + 4, wsrc + 4);
        #pragma unroll
        for (int j = 0; j < 2; j++) {
            const int idx = t + j * 256;
            const int kk = idx >> 5, nf = idx & 31;
            const int kg = k0 + kk;
            const float* src;
            if (MODE == 2 || MODE == 3) {
                const int n = bn + nf * 4;
                const int b = n >> 12, hw = n & 4095;
                src = &X[((size_t)b * CDIM + kg) * 4096 + hw];
            } else {
                src = &X[(size_t)kg * Nld + bn + nf * 4];
            }
            cp16(Bs + st * B_STAGE + kk * B_STRIDE + nf * 4, src);
        }
    };

    issue(0); CP_COMMIT();
    if (NC > 1) issue(1);
    CP_COMMIT();

    for (int c = 0; c < NC; c++) {
        if (c + 2 < NC) issue(c + 2);
        CP_COMMIT();
        CP_WAIT2();                    // chunk c landed (<=2 newer outstanding)
        __syncthreads();

        const int st = c % NSTAGE;
        const float* Ab = As + st * A_STAGE;
        const float* Bb = Bs + st * B_STAGE;

        #pragma unroll
        for (int ks = 0; ks < 2; ks++) {
            const int kb = ks * 8;

            uint32_t bhi[4][2], blo[4][2];
            #pragma unroll
            for (int nt = 0; nt < 4; nt++) {
                const int col = wn + nt * 8 + gid;
                float b0 = Bb[(kb + tig) * B_STRIDE + col];
                float b1 = Bb[(kb + tig + 4) * B_STRIDE + col];
                if (MODE == 1) { b0 = fmaxf(b0, 0.f); b1 = fmaxf(b1, 0.f); }
                tf32_split(b0, bhi[nt][0], blo[nt][0]);
                tf32_split(b1, bhi[nt][1], blo[nt][1]);
            }

            #pragma unroll
            for (int mg = 0; mg < 2; mg++) {       // mt pairs {0,1}, {2,3}
                uint32_t ahi[2][4], alo[2][4];
                #pragma unroll
                for (int m2 = 0; m2 < 2; m2++) {
                    const int row = wm + (mg * 2 + m2) * 16 + gid;
                    tf32_split(Ab[row * A_STRIDE + kb + tig],           ahi[m2][0], alo[m2][0]);
                    tf32_split(Ab[(row + 8) * A_STRIDE + kb + tig],     ahi[m2][1], alo[m2][1]);
                    tf32_split(Ab[row * A_STRIDE + kb + tig + 4],       ahi[m2][2], alo[m2][2]);
                    tf32_split(Ab[(row + 8) * A_STRIDE + kb + tig + 4], ahi[m2][3], alo[m2][3]);
                }
                // pass-major: each acc reused only every 8 MMAs
                #pragma unroll
                for (int m2 = 0; m2 < 2; m2++)
                    #pragma unroll
                    for (int nt = 0; nt < 4; nt++)
                        mma_tf32(acc[mg * 2 + m2][nt], ahi[m2], bhi[nt]);
                #pragma unroll
                for (int m2 = 0; m2 < 2; m2++)
                    #pragma unroll
                    for (int nt = 0; nt < 4; nt++)
                        mma_tf32(acc[mg * 2 + m2][nt], alo[m2], bhi[nt]);
                #pragma unroll
                for (int m2 = 0; m2 < 2; m2++)
                    #pragma unroll
                    for (int nt = 0; nt < 4; nt++)
                        mma_tf32(acc[mg * 2 + m2][nt], ahi[m2], blo[nt]);
            }
        }
        __syncthreads();               // done reading stage before overwrite
    }

    // --- epilogue ---
    #pragma unroll
    for (int mt = 0; mt < 4; mt++) {
        const int r0 = bm + wm + mt * 16 + gid;
        const int r1 = r0 + 8;
        const float s0 = scale[r0], bi0 = bias[r0];
        const float s1 = scale[r1], bi1 = bias[r1];
        #pragma unroll
        for (int nt = 0; nt < 4; nt++) {
            const int n0 = bn + wn + nt * 8 + tig * 2;
            float v00 = acc[mt][nt][0] * s0 + bi0;
            float v01 = acc[mt][nt][1] * s0 + bi0;
            float v10 = acc[mt][nt][2] * s1 + bi1;
            float v11 = acc[mt][nt][3] * s1 + bi1;
            if (MODE == 2) {
                const int b = n0 >> 12, hw = n0 & 4095;
                const int h = hw >> 6, w = hw & 63;
                const int o = (b << 6);
                const float re0 = e0[r0 * NAX + o + h];
                const float re1 = e0[r1 * NAX + o + h];
                const float c0a = e1[r0 * NAX + o + w];
                const float c0b = e1[r0 * NAX + o + w + 1];
                const float c1a = e1[r1 * NAX + o + w];
                const float c1b = e1[r1 * NAX + o + w + 1];
                float2 u0, u1;
                u0.x = fmaxf(v00 + re0 + c0a, 0.f);
                u0.y = fmaxf(v01 + re0 + c0b, 0.f);
                u1.x = fmaxf(v10 + re1 + c1a, 0.f);
                u1.y = fmaxf(v11 + re1 + c1b, 0.f);
                *reinterpret_cast<float2*>(&out[(size_t)r0 * Nld + n0]) = u0;
                *reinterpret_cast<float2*>(&out[(size_t)r1 * Nld + n0]) = u1;
            } else if (MODE == 4) {
                const int b = n0 >> 12, hw = n0 & 4095;
                float2 p0 = *reinterpret_cast<const float2*>(&e0[(size_t)r0 * Nld + n0]);
                float2 p1 = *reinterpret_cast<const float2*>(&e0[(size_t)r1 * Nld + n0]);
                float2 u0, u1;
                u0.x = fminf(fmaxf(v00 + 3.f, 0.f), 6.f) * (1.f / 6.f) * p0.x;
                u0.y = fminf(fmaxf(v01 + 3.f, 0.f), 6.f) * (1.f / 6.f) * p0.y;
                u1.x = fminf(fmaxf(v10 + 3.f, 0.f), 6.f) * (1.f / 6.f) * p1.x;
                u1.y = fminf(fmaxf(v11 + 3.f, 0.f), 6.f) * (1.f / 6.f) * p1.y;
                *reinterpret_cast<float2*>(
                    &out[((size_t)b * CDIM + r0) * 4096 + hw]) = u0;
                *reinterpret_cast<float2*>(
                    &out[((size_t)b * CDIM + r1) * 4096 + hw]) = u1;
            } else {
                float2 u0, u1;
                u0.x = v00; u0.y = v01;
                u1.x = v10; u1.y = v11;
                *reinterpret_cast<float2*>(&out[(size_t)r0 * Nld + n0]) = u0;
                *reinterpret_cast<float2*>(&out[(size_t)r1 * Nld + n0]) = u1;
            }
        }
    }
}

// ---------------------------------------------------------------------------
// GEMM kernel wrappers (dynamic smem, 3 stages)
// ---------------------------------------------------------------------------
template <int MODE>
__global__ void __launch_bounds__(256, 2)
tc_gemm(const float* __restrict__ Wm, const float* __restrict__ X,
        const float* __restrict__ scale, const float* __restrict__ bias,
        float* __restrict__ out, int K,
        const float* __restrict__ e0, const float* __restrict__ e1)
{
    extern __shared__ float dsm[];
    gemm_core<MODE>(Wm, X, scale, bias, out, K, e0, e1,
                    blockIdx.y * 128, blockIdx.x * 128, gridDim.x * 128,
                    dsm, dsm + NSTAGE * A_STAGE);
}

// batched q/k/v projection: z=0 -> q (M=128), z=1 -> k (M=128), z=2 -> v (M=512)
__global__ void __launch_bounds__(256, 2)
tc_gemm_qkv(const float* __restrict__ wq, const float* __restrict__ sq,
            const float* __restrict__ bq, float* __restrict__ oq,
            const float* __restrict__ wk, const float* __restrict__ sk,
            const float* __restrict__ bk, float* __restrict__ ok,
            const float* __restrict__ wv, const float* __restrict__ sv,
            const float* __restrict__ bv, float* __restrict__ ov,
            const float* __restrict__ X)
{
    extern __shared__ float dsm[];
    const int z = blockIdx.z;
    const int yv = (z < 2) ? 1 : 4;
    if ((int)blockIdx.y >= yv) return;
    const float* W = (z == 0) ? wq : (z == 1) ? wk : wv;
    const float* s = (z == 0) ? sq : (z == 1) ? sk : sv;
    const float* b = (z == 0) ? bq : (z == 1) ? bk : bv;
    float*       o = (z == 0) ? oq : (z == 1) ? ok : ov;
    gemm_core<0>(W, X, s, b, o, CDIM, nullptr, nullptr,
                 blockIdx.y * 128, blockIdx.x * 128, NAX2,
                 dsm, dsm + NSTAGE * A_STAGE);
}

// batched row/col cbn: z selects weight set + xx/rout slab
__global__ void __launch_bounds__(256, 2)
tc_gemm_rowcol(const float* __restrict__ w_row, const float* __restrict__ s_row,
               const float* __restrict__ b_row,
               const float* __restrict__ w_col, const float* __restrict__ s_col,
               const float* __restrict__ b_col,
               const float* __restrict__ xx, float* __restrict__ rout)
{
    extern __shared__ float dsm[];
    const int z = blockIdx.z;
    const float* W = z ? w_col : w_row;
    const float* s = z ? s_col : s_row;
    const float* b = z ? b_col : b_row;
    const float* X = xx + (size_t)z * DHD * NAX;
    float*       o = rout + (size_t)z * DHD * NAX;
    gemm_core<1>(W, X, s, b, o, DHD, nullptr, nullptr,
                 blockIdx.y * 128, blockIdx.x * 128, NAX,
                 dsm, dsm + NSTAGE * A_STAGE);
}

// ---------------------------------------------------------------------------
// K1: row/col means of x -> packed [256][2048] (axis 0 = row, axis 1 = col)
// ---------------------------------------------------------------------------
__global__ void mean_kernel(const float* __restrict__ x)
{
    __shared__ float s[64 * 65];
    const int blk = blockIdx.x;                // b*256 + c
    const float* base = x + (size_t)blk * 4096;
    const int t = threadIdx.x;                 // 64 threads

    #pragma unroll
    for (int i = 0; i < 64; i++) s[i * 65 + t] = base[i * 64 + t];
    __syncthreads();

    float rs = 0.f, cs = 0.f;
    #pragma unroll
    for (int i = 0; i < 64; i++) {
        rs += s[t * 65 + i];
        cs += s[i * 65 + t];
    }
    const int b = blk >> 8;
    const int c = blk & 255;
    g_xmean[c * NAX2 + b * 64 + t]        = rs * (1.f / 64.f);
    g_xmean[c * NAX2 + 1024 + b * 64 + t] = cs * (1.f / 64.f);
}

// ---------------------------------------------------------------------------
// K3: axial attention. One block per (axis, b, head); 64 threads.
// ---------------------------------------------------------------------------
__device__ __forceinline__ float pos_interp(const float* __restrict__ p,
                                            int ch, int i)
{
    float c = (i + 0.5f) * 0.25f - 0.5f;
    c = fminf(fmaxf(c, 0.f), 15.f);
    int lo = (int)floorf(c);
    int hi = min(lo + 1, 15);
    float tt = c - (float)lo;
    const float* row = p + ch * 16;
    return row[lo] * (1.f - tt) + row[hi] * tt;
}

__global__ void attn_kernel(const float* __restrict__ pos_rowq,
                            const float* __restrict__ pos_rowk,
                            const float* __restrict__ pos_colq,
                            const float* __restrict__ pos_colk)
{
    const int blk  = blockIdx.x;          // axis*128 + b*8 + head
    const int axis = blk >> 7;
    const int b    = (blk >> 3) & 15;
    const int head = blk & 7;
    const float* pq = axis ? pos_colq : pos_rowq;
    const float* pk = axis ? pos_colk : pos_rowk;
    const int col0 = axis * 1024 + b * 64;

    __shared__ float ks[KEYD][64];
    __shared__ float vs[DV][64];
    const int t = threadIdx.x;            // 64

    float qr[KEYD];
    #pragma unroll
    for (int c = 0; c < KEYD; c++) {
        const int ch = head * KEYD + c;
        ks[c][t] = g_ke[ch * NAX2 + col0 + t] + pos_interp(pk, ch, t);
        qr[c]    = g_qe[ch * NAX2 + col0 + t] + pos_interp(pq, ch, t);
    }
    #pragma unroll
    for (int d = 0; d < DV; d++)
        vs[d][t] = g_ve[(head * DV + d) * NAX2 + col0 + t];
    __syncthreads();

    float S[64];
    float mx = -1e30f;
    #pragma unroll
    for (int j = 0; j < 64; j++) {
        float s = 0.f;
        #pragma unroll
        for (int c = 0; c < KEYD; c++) s += qr[c] * ks[c][j];
        s *= ATTN_SCALE;
        S[j] = s;
        mx = fmaxf(mx, s);
    }
    float sum = 0.f;
    #pragma unroll
    for (int j = 0; j < 64; j++) { S[j] = __expf(S[j] - mx); sum += S[j]; }
    const float inv = 1.f / sum;

    float* xo = g_xx[axis];
    #pragma unroll
    for (int d = 0; d < DV; d++) {
        float o = 0.f;
        #pragma unroll
        for (int j = 0; j < 64; j++) o += S[j] * vs[d][j];
        xo[(head * DV + d) * NAX + b * 64 + t] = o * inv;
    }
}

// ---------------------------------------------------------------------------
// K6b: depthwise 3x3 (SAME, zero pad) + affine + relu.  g1 -> g2
// ---------------------------------------------------------------------------
__global__ void dw_kernel(const float* __restrict__ wdw,
                          const float* __restrict__ sdw,
                          const float* __restrict__ bdw)
{
    const long long idx = (long long)blockIdx.x * blockDim.x + threadIdx.x;
    if (idx >= (long long)CDIM * NPIX) return;
    const int n = (int)(idx & (NPIX - 1));
    const int c = (int)(idx >> 16);
    const int b = n >> 12, hw = n & 4095;
    const int h = hw >> 6, w = hw & 63;
    const float* base = g_g1 + (size_t)c * NPIX + (size_t)b * 4096;
    const float* wk = wdw + c * 9;

    float acc = 0.f;
    #pragma unroll
    for (int dy = 0; dy < 3; dy++) {
        const int hh = h + dy - 1;
        if (hh < 0 || hh > 63) continue;
        #pragma unroll
        for (int dx = 0; dx < 3; dx++) {
            const int ww = w + dx - 1;
            if (ww < 0 || ww > 63) continue;
            acc += base[hh * 64 + ww] * wk[dy * 3 + dx];
        }
    }
    float v = acc * sdw[c] + bdw[c];
    g_g2[idx] = fmaxf(v, 0.f);
}

// ---------------------------------------------------------------------------
// Host launcher
// ---------------------------------------------------------------------------
extern "C" void kernel_launch(void* const* d_in, const int* in_sizes, int n_in,
                              void* d_out, int out_size)
{
    const float* x        = (const float*)d_in[0];
    const float* wq       = (const float*)d_in[1];
    const float* sq       = (const float*)d_in[2];
    const float* bq       = (const float*)d_in[3];
    const float* wk       = (const float*)d_in[4];
    const float* sk       = (const float*)d_in[5];
    const float* bk       = (const float*)d_in[6];
    const float* wv       = (const float*)d_in[7];
    const float* sv       = (const float*)d_in[8];
    const float* bv       = (const float*)d_in[9];
    const float* pos_rowq = (const float*)d_in[10];
    const float* pos_rowk = (const float*)d_in[11];
    const float* pos_colq = (const float*)d_in[12];
    const float* pos_colk = (const float*)d_in[13];
    const float* w_row    = (const float*)d_in[14];
    const float* s_row    = (const float*)d_in[15];
    const float* b_row    = (const float*)d_in[16];
    const float* w_col    = (const float*)d_in[17];
    const float* s_col    = (const float*)d_in[18];
    const float* b_col    = (const float*)d_in[19];
    const float* w_proj   = (const float*)d_in[20];
    const float* s_proj   = (const float*)d_in[21];
    const float* b_proj   = (const float*)d_in[22];
    const float* w_sc     = (const float*)d_in[23];
    const float* s_sc     = (const float*)d_in[24];
    const float* b_sc     = (const float*)d_in[25];
    const float* w_dw     = (const float*)d_in[26];
    const float* s_dw     = (const float*)d_in[27];
    const float* b_dw     = (const float*)d_in[28];
    const float* w_pw     = (const float*)d_in[29];
    const float* s_pw     = (const float*)d_in[30];
    const float* b_pw     = (const float*)d_in[31];

    float *p_xm, *p_qe, *p_ke, *p_ve, *p_xx, *p_rout, *p_A, *p_g1, *p_g2, *p_P;
    cudaGetSymbolAddress((void**)&p_xm,   g_xmean);
    cudaGetSymbolAddress((void**)&p_qe,   g_qe);
    cudaGetSymbolAddress((void**)&p_ke,   g_ke);
    cudaGetSymbolAddress((void**)&p_ve,   g_ve);
    cudaGetSymbolAddress((void**)&p_xx,   g_xx);
    cudaGetSymbolAddress((void**)&p_rout, g_rout);
    cudaGetSymbolAddress((void**)&p_A,    g_A);
    cudaGetSymbolAddress((void**)&p_g1,   g_g1);
    cudaGetSymbolAddress((void**)&p_g2,   g_g2);
    cudaGetSymbolAddress((void**)&p_P,    g_P);

    static int smem_set = 0;
    if (!smem_set) {
        cudaFuncSetAttribute(tc_gemm<0>, cudaFuncAttributeMaxDynamicSharedMemorySize, SMEM_SZ);
        cudaFuncSetAttribute(tc_gemm<2>, cudaFuncAttributeMaxDynamicSharedMemorySize, SMEM_SZ);
        cudaFuncSetAttribute(tc_gemm<3>, cudaFuncAttributeMaxDynamicSharedMemorySize, SMEM_SZ);
        cudaFuncSetAttribute(tc_gemm<4>, cudaFuncAttributeMaxDynamicSharedMemorySize, SMEM_SZ);
        cudaFuncSetAttribute(tc_gemm_qkv, cudaFuncAttributeMaxDynamicSharedMemorySize, SMEM_SZ);
        cudaFuncSetAttribute(tc_gemm_rowcol, cudaFuncAttributeMaxDynamicSharedMemorySize, SMEM_SZ);
        smem_set = 1;
    }

    // K1: means (both axes into one [256][2048] buffer)
    mean_kernel<<<BB * CDIM, 64>>>(x);

    // K2: q/k/v projections, single batched launch (z = q,k,v)
    tc_gemm_qkv<<<dim3(NAX2 / 128, 4, 3), 256, SMEM_SZ>>>(
        wq, sq, bq, p_qe, wk, sk, bk, p_ke, wv, sv, bv, p_ve, p_xm);

    // K3: axial attention (both axes)
    attn_kernel<<<2 * BB * NHEADS, 64>>>(pos_rowq, pos_rowk, pos_colq, pos_colk);

    // K4: w_row / w_col cbn on relu(xx), single batched launch
    tc_gemm_rowcol<<<dim3(NAX / 128, DHD / 128, 2), 256, SMEM_SZ>>>(
        w_row, s_row, b_row, w_col, s_col, b_col, p_xx, p_rout);

    // K5: A = relu(v + row + col)   (big GEMM over all pixels)
    tc_gemm<2><<<dim3(NPIX / 128, DHD / 128), 256, SMEM_SZ>>>(
        wv, x, sv, bv, p_A, CDIM, p_rout, p_rout + (size_t)DHD * NAX);

    // K5g: g1 = cbn(x, w_sc)
    tc_gemm<3><<<dim3(NPIX / 128, CDIM / 128), 256, SMEM_SZ>>>(
        w_sc, x, s_sc, b_sc, p_g1, CDIM, nullptr, nullptr);

    // K6a: P = cbn(A, w_proj)
    tc_gemm<0><<<dim3(NPIX / 128, CDIM / 128), 256, SMEM_SZ>>>(
        w_proj, p_A, s_proj, b_proj, p_P, DHD, nullptr, nullptr);

    // K6b: depthwise 3x3 + affine + relu
    dw_kernel<<<(CDIM * NPIX) / 256, 256>>>(w_dw, s_dw, b_dw);

    // K6c: out = h_sigmoid(cbn(g2, w_pw)) * P  (scatter to NCHW)
    tc_gemm<4><<<dim3(NPIX / 128, CDIM / 128), 256, SMEM_SZ>>>(
        w_pw, p_g2, s_pw, b_pw, (float*)d_out, CDIM, p_P, nullptr);
}

// round 14
// speedup vs baseline: 2.5852x; 1.0099x over previous
#include <cuda_runtime.h>
#include <cstdint>
#include <cstddef>

// ---------------------------------------------------------------------------
// Problem constants
// ---------------------------------------------------------------------------
#define BB     16
#define CDIM   256
#define HDIM   64
#define WDIM   64
#define NHKD   128
#define DHD    512
#define NPIX   65536        // BB*HDIM*WDIM
#define NAX    1024         // BB*64
#define NAX2   2048         // both axes packed
#define NHEADS 8
#define KEYD   16
#define DV     64
#define ATTN_SCALE 0.25f

#define A_STRIDE 20         // floats per A smem row (16 data + 4 pad)
#define B_STRIDE 136        // floats per B smem row (128 data + 8 pad)
#define A_STAGE  (128 * A_STRIDE)
#define B_STAGE  (16 * B_STRIDE)
#define NSTAGE   4
#define SMEM_SZ  (NSTAGE * (A_STAGE + B_STAGE) * 4)   // 75776 bytes

// ---------------------------------------------------------------------------
// Scratch (device globals; no allocation allowed)
// ---------------------------------------------------------------------------
__device__ float g_xmean[CDIM * NAX2];         // [c][axis*1024 + b*64 + p]
__device__ float g_qe[NHKD * NAX2];
__device__ float g_ke[NHKD * NAX2];
__device__ float g_ve[DHD * NAX2];
__device__ float g_xx[2][DHD * NAX];           // attention output (pre-relu)
__device__ float g_rout[2][DHD * NAX];         // after w_row / w_col cbn
__device__ float g_A[(size_t)DHD * NPIX];      // relu(v + row + col), packed [m][n]
__device__ float g_g1[(size_t)CDIM * NPIX];    // gate after w_sc cbn, packed [c][n]
__device__ float g_g2[(size_t)CDIM * NPIX];    // relu(dw(g1)), packed [c][n]
__device__ float g_P[(size_t)CDIM * NPIX];     // proj output, packed [m][n]

// ---------------------------------------------------------------------------
// PTX helpers
// ---------------------------------------------------------------------------
__device__ __forceinline__ void mma_tf32(float* c, const uint32_t* a,
                                         const uint32_t* b)
{
    asm volatile(
        "mma.sync.aligned.m16n8k8.row.col.f32.tf32.tf32.f32 "
        "{%0,%1,%2,%3}, {%4,%5,%6,%7}, {%8,%9}, {%0,%1,%2,%3};"
        : "+f"(c[0]), "+f"(c[1]), "+f"(c[2]), "+f"(c[3])
        : "r"(a[0]), "r"(a[1]), "r"(a[2]), "r"(a[3]),
          "r"(b[0]), "r"(b[1]));
}

__device__ __forceinline__ uint32_t tf32_rna(float x)
{
    uint32_t r;
    asm("cvt.rna.tf32.f32 %0, %1;" : "=r"(r) : "f"(x));
    return r;
}

__device__ __forceinline__ void tf32_split(float x, uint32_t& hi, uint32_t& lo)
{
    hi = tf32_rna(x);
    lo = __float_as_uint(x - __uint_as_float(hi));
}

__device__ __forceinline__ void cp16(void* dst_smem, const void* src)
{
    uint32_t d = (uint32_t)__cvta_generic_to_shared(dst_smem);
    asm volatile("cp.async.cg.shared.global [%0], [%1], 16;"
                 :: "r"(d), "l"(src));
}
#define CP_COMMIT() asm volatile("cp.async.commit_group;" ::: "memory")
#define CP_WAIT3()  asm volatile("cp.async.wait_group 3;" ::: "memory")

// ---------------------------------------------------------------------------
// 3xTF32 GEMM core: out = epilogue( W[M,K] @ X[K,N] ), ~fp32 accuracy.
// CTA tile 128(M) x 128(N); K-chunk 16; cp.async 4-stage pipeline.
// 256 threads = 8 warps (2x4); warp tile 64x32.
// MODE 0: X packed,           out = acc*s+b                        (packed)
// MODE 1: X packed + relu-in, out = acc*s+b                        (packed)
// MODE 2: X = x (BCHW, K=256) out = relu(acc*s+b + e0[h] + e1[w])  (packed)
// MODE 3: X = x (BCHW, K=256) out = acc*s+b                        (packed)
// MODE 4: X packed,           out = h_sigmoid(acc*s+b) * e0, scatter to BCHW
// ---------------------------------------------------------------------------
template <int MODE>
__device__ __forceinline__ void gemm_core(
    const float* __restrict__ Wm, const float* __restrict__ X,
    const float* __restrict__ scale, const float* __restrict__ bias,
    float* __restrict__ out, int K,
    const float* __restrict__ e0, const float* __restrict__ e1,
    int bm, int bn, int Nld, float* As, float* Bs)
{
    const int t = threadIdx.x;         // 256
    const int warp = t >> 5, lane = t & 31;
    const int wm = (warp >> 2) * 64;   // 0 | 64
    const int wn = (warp & 3) * 32;    // 0..96
    const int gid = lane >> 2;         // 0..7
    const int tig = lane & 3;          // 0..3

    const int mA = t >> 1;             // 0..127
    const int kq = (t & 1) * 8;        // 0 | 8

    float acc[4][4][4];
    #pragma unroll
    for (int i = 0; i < 4; i++)
        #pragma unroll
        for (int j = 0; j < 4; j++)
            #pragma unroll
            for (int r = 0; r < 4; r++) acc[i][j][r] = 0.f;

    const int NC = K >> 4;

    // stage issue: chunk c -> buffer c % NSTAGE
    auto issue = [&](int c) {
        const int st = c % NSTAGE;
        const int k0 = c << 4;
        const float* wsrc = &Wm[(size_t)(bm + mA) * K + k0 + kq];
        float* ad = As + st * A_STAGE + mA * A_STRIDE + kq;
        cp16(ad, wsrc);
        cp16(ad + 4, wsrc + 4);
        #pragma unroll
        for (int j = 0; j < 2; j++) {
            const int idx = t + j * 256;
            const int kk = idx >> 5, nf = idx & 31;
            const int kg = k0 + kk;
            const float* src;
            if (MODE == 2 || MODE == 3) {
                const int n = bn + nf * 4;
                const int b = n >> 12, hw = n & 4095;
                src = &X[((size_t)b * CDIM + kg) * 4096 + hw];
            } else {
                src = &X[(size_t)kg * Nld + bn + nf * 4];
            }
            cp16(Bs + st * B_STAGE + kk * B_STRIDE + nf * 4, src);
        }
    };

    issue(0); CP_COMMIT();
    if (NC > 1) issue(1);
    CP_COMMIT();
    if (NC > 2) issue(2);
    CP_COMMIT();

    for (int c = 0; c < NC; c++) {
        if (c + 3 < NC) issue(c + 3);
        CP_COMMIT();
        CP_WAIT3();                    // chunk c landed (<=3 newer outstanding)
        __syncthreads();

        const int st = c % NSTAGE;
        const float* Ab = As + st * A_STAGE;
        const float* Bb = Bs + st * B_STAGE;

        #pragma unroll
        for (int ks = 0; ks < 2; ks++) {
            const int kb = ks * 8;

            uint32_t bhi[4][2], blo[4][2];
            #pragma unroll
            for (int nt = 0; nt < 4; nt++) {
                const int col = wn + nt * 8 + gid;
                float b0 = Bb[(kb + tig) * B_STRIDE + col];
                float b1 = Bb[(kb + tig + 4) * B_STRIDE + col];
                if (MODE == 1) { b0 = fmaxf(b0, 0.f); b1 = fmaxf(b1, 0.f); }
                tf32_split(b0, bhi[nt][0], blo[nt][0]);
                tf32_split(b1, bhi[nt][1], blo[nt][1]);
            }

            #pragma unroll
            for (int mg = 0; mg < 2; mg++) {       // mt pairs {0,1}, {2,3}
                uint32_t ahi[2][4], alo[2][4];
                #pragma unroll
                for (int m2 = 0; m2 < 2; m2++) {
                    const int row = wm + (mg * 2 + m2) * 16 + gid;
                    tf32_split(Ab[row * A_STRIDE + kb + tig],           ahi[m2][0], alo[m2][0]);
                    tf32_split(Ab[(row + 8) * A_STRIDE + kb + tig],     ahi[m2][1], alo[m2][1]);
                    tf32_split(Ab[row * A_STRIDE + kb + tig + 4],       ahi[m2][2], alo[m2][2]);
                    tf32_split(Ab[(row + 8) * A_STRIDE + kb + tig + 4], ahi[m2][3], alo[m2][3]);
                }
                // pass-major: each acc reused only every 8 MMAs
                #pragma unroll
                for (int m2 = 0; m2 < 2; m2++)
                    #pragma unroll
                    for (int nt = 0; nt < 4; nt++)
                        mma_tf32(acc[mg * 2 + m2][nt], ahi[m2], bhi[nt]);
                #pragma unroll
                for (int m2 = 0; m2 < 2; m2++)
                    #pragma unroll
                    for (int nt = 0; nt < 4; nt++)
                        mma_tf32(acc[mg * 2 + m2][nt], alo[m2], bhi[nt]);
                #pragma unroll
                for (int m2 = 0; m2 < 2; m2++)
                    #pragma unroll
                    for (int nt = 0; nt < 4; nt++)
                        mma_tf32(acc[mg * 2 + m2][nt], ahi[m2], blo[nt]);
            }
        }
        __syncthreads();               // done reading stage before overwrite
    }

    // --- epilogue ---
    #pragma unroll
    for (int mt = 0; mt < 4; mt++) {
        const int r0 = bm + wm + mt * 16 + gid;
        const int r1 = r0 + 8;
        const float s0 = scale[r0], bi0 = bias[r0];
        const float s1 = scale[r1], bi1 = bias[r1];
        #pragma unroll
        for (int nt = 0; nt < 4; nt++) {
            const int n0 = bn + wn + nt * 8 + tig * 2;
            float v00 = acc[mt][nt][0] * s0 + bi0;
            float v01 = acc[mt][nt][1] * s0 + bi0;
            float v10 = acc[mt][nt][2] * s1 + bi1;
            float v11 = acc[mt][nt][3] * s1 + bi1;
            if (MODE == 2) {
                const int b = n0 >> 12, hw = n0 & 4095;
                const int h = hw >> 6, w = hw & 63;
                const int o = (b << 6);
                const float re0 = e0[r0 * NAX + o + h];
                const float re1 = e0[r1 * NAX + o + h];
                const float c0a = e1[r0 * NAX + o + w];
                const float c0b = e1[r0 * NAX + o + w + 1];
                const float c1a = e1[r1 * NAX + o + w];
                const float c1b = e1[r1 * NAX + o + w + 1];
                float2 u0, u1;
                u0.x = fmaxf(v00 + re0 + c0a, 0.f);
                u0.y = fmaxf(v01 + re0 + c0b, 0.f);
                u1.x = fmaxf(v10 + re1 + c1a, 0.f);
                u1.y = fmaxf(v11 + re1 + c1b, 0.f);
                *reinterpret_cast<float2*>(&out[(size_t)r0 * Nld + n0]) = u0;
                *reinterpret_cast<float2*>(&out[(size_t)r1 * Nld + n0]) = u1;
            } else if (MODE == 4) {
                const int b = n0 >> 12, hw = n0 & 4095;
                float2 p0 = *reinterpret_cast<const float2*>(&e0[(size_t)r0 * Nld + n0]);
                float2 p1 = *reinterpret_cast<const float2*>(&e0[(size_t)r1 * Nld + n0]);
                float2 u0, u1;
                u0.x = fminf(fmaxf(v00 + 3.f, 0.f), 6.f) * (1.f / 6.f) * p0.x;
                u0.y = fminf(fmaxf(v01 + 3.f, 0.f), 6.f) * (1.f / 6.f) * p0.y;
                u1.x = fminf(fmaxf(v10 + 3.f, 0.f), 6.f) * (1.f / 6.f) * p1.x;
                u1.y = fminf(fmaxf(v11 + 3.f, 0.f), 6.f) * (1.f / 6.f) * p1.y;
                *reinterpret_cast<float2*>(
                    &out[((size_t)b * CDIM + r0) * 4096 + hw]) = u0;
                *reinterpret_cast<float2*>(
                    &out[((size_t)b * CDIM + r1) * 4096 + hw]) = u1;
            } else {
                float2 u0, u1;
                u0.x = v00; u0.y = v01;
                u1.x = v10; u1.y = v11;
                *reinterpret_cast<float2*>(&out[(size_t)r0 * Nld + n0]) = u0;
                *reinterpret_cast<float2*>(&out[(size_t)r1 * Nld + n0]) = u1;
            }
        }
    }
}

// ---------------------------------------------------------------------------
// GEMM kernel wrappers (dynamic smem, 4 stages)
// Grid layout: (x = M-blocks, y = N-blocks) so CTAs sharing an N-slab of X
// are launch-adjacent -> X slab read hits L2 for all but the first.
// ---------------------------------------------------------------------------
template <int MODE>
__global__ void __launch_bounds__(256, 2)
tc_gemm(const float* __restrict__ Wm, const float* __restrict__ X,
        const float* __restrict__ scale, const float* __restrict__ bias,
        float* __restrict__ out, int K,
        const float* __restrict__ e0, const float* __restrict__ e1)
{
    extern __shared__ float dsm[];
    gemm_core<MODE>(Wm, X, scale, bias, out, K, e0, e1,
                    blockIdx.x * 128, blockIdx.y * 128, gridDim.y * 128,
                    dsm, dsm + NSTAGE * A_STAGE);
}

// batched q/k/v projection: z=0 -> q (M=128), z=1 -> k (M=128), z=2 -> v (M=512)
__global__ void __launch_bounds__(256, 2)
tc_gemm_qkv(const float* __restrict__ wq, const float* __restrict__ sq,
            const float* __restrict__ bq, float* __restrict__ oq,
            const float* __restrict__ wk, const float* __restrict__ sk,
            const float* __restrict__ bk, float* __restrict__ ok,
            const float* __restrict__ wv, const float* __restrict__ sv,
            const float* __restrict__ bv, float* __restrict__ ov,
            const float* __restrict__ X)
{
    extern __shared__ float dsm[];
    const int z = blockIdx.z;
    const int xv = (z < 2) ? 1 : 4;    // m-blocks valid for this z
    if ((int)blockIdx.x >= xv) return;
    const float* W = (z == 0) ? wq : (z == 1) ? wk : wv;
    const float* s = (z == 0) ? sq : (z == 1) ? sk : sv;
    const float* b = (z == 0) ? bq : (z == 1) ? bk : bv;
    float*       o = (z == 0) ? oq : (z == 1) ? ok : ov;
    gemm_core<0>(W, X, s, b, o, CDIM, nullptr, nullptr,
                 blockIdx.x * 128, blockIdx.y * 128, NAX2,
                 dsm, dsm + NSTAGE * A_STAGE);
}

// batched row/col cbn: z selects weight set + xx/rout slab
__global__ void __launch_bounds__(256, 2)
tc_gemm_rowcol(const float* __restrict__ w_row, const float* __restrict__ s_row,
               const float* __restrict__ b_row,
               const float* __restrict__ w_col, const float* __restrict__ s_col,
               const float* __restrict__ b_col,
               const float* __restrict__ xx, float* __restrict__ rout)
{
    extern __shared__ float dsm[];
    const int z = blockIdx.z;
    const float* W = z ? w_col : w_row;
    const float* s = z ? s_col : s_row;
    const float* b = z ? b_col : b_row;
    const float* X = xx + (size_t)z * DHD * NAX;
    float*       o = rout + (size_t)z * DHD * NAX;
    gemm_core<1>(W, X, s, b, o, DHD, nullptr, nullptr,
                 blockIdx.x * 128, blockIdx.y * 128, NAX,
                 dsm, dsm + NSTAGE * A_STAGE);
}

// ---------------------------------------------------------------------------
// K1: row/col means of x -> packed [256][2048] (axis 0 = row, axis 1 = col)
// ---------------------------------------------------------------------------
__global__ void mean_kernel(const float* __restrict__ x)
{
    __shared__ float s[64 * 65];
    const int blk = blockIdx.x;                // b*256 + c
    const float* base = x + (size_t)blk * 4096;
    const int t = threadIdx.x;                 // 64 threads

    #pragma unroll
    for (int i = 0; i < 64; i++) s[i * 65 + t] = base[i * 64 + t];
    __syncthreads();

    float rs = 0.f, cs = 0.f;
    #pragma unroll
    for (int i = 0; i < 64; i++) {
        rs += s[t * 65 + i];
        cs += s[i * 65 + t];
    }
    const int b = blk >> 8;
    const int c = blk & 255;
    g_xmean[c * NAX2 + b * 64 + t]        = rs * (1.f / 64.f);
    g_xmean[c * NAX2 + 1024 + b * 64 + t] = cs * (1.f / 64.f);
}

// ---------------------------------------------------------------------------
// K3: axial attention. One block per (axis, b, head); 64 threads.
// ---------------------------------------------------------------------------
__device__ __forceinline__ float pos_interp(const float* __restrict__ p,
                                            int ch, int i)
{
    float c = (i + 0.5f) * 0.25f - 0.5f;
    c = fminf(fmaxf(c, 0.f), 15.f);
    int lo = (int)floorf(c);
    int hi = min(lo + 1, 15);
    float tt = c - (float)lo;
    const float* row = p + ch * 16;
    return row[lo] * (1.f - tt) + row[hi] * tt;
}

__global__ void attn_kernel(const float* __restrict__ pos_rowq,
                            const float* __restrict__ pos_rowk,
                            const float* __restrict__ pos_colq,
                            const float* __restrict__ pos_colk)
{
    const int blk  = blockIdx.x;          // axis*128 + b*8 + head
    const int axis = blk >> 7;
    const int b    = (blk >> 3) & 15;
    const int head = blk & 7;
    const float* pq = axis ? pos_colq : pos_rowq;
    const float* pk = axis ? pos_colk : pos_rowk;
    const int col0 = axis * 1024 + b * 64;

    __shared__ float ks[KEYD][64];
    __shared__ float vs[DV][64];
    const int t = threadIdx.x;            // 64

    float qr[KEYD];
    #pragma unroll
    for (int c = 0; c < KEYD; c++) {
        const int ch = head * KEYD + c;
        ks[c][t] = g_ke[ch * NAX2 + col0 + t] + pos_interp(pk, ch, t);
        qr[c]    = g_qe[ch * NAX2 + col0 + t] + pos_interp(pq, ch, t);
    }
    #pragma unroll
    for (int d = 0; d < DV; d++)
        vs[d][t] = g_ve[(head * DV + d) * NAX2 + col0 + t];
    __syncthreads();

    float S[64];
    float mx = -1e30f;
    #pragma unroll
    for (int j = 0; j < 64; j++) {
        float s = 0.f;
        #pragma unroll
        for (int c = 0; c < KEYD; c++) s += qr[c] * ks[c][j];
        s *= ATTN_SCALE;
        S[j] = s;
        mx = fmaxf(mx, s);
    }
    float sum = 0.f;
    #pragma unroll
    for (int j = 0; j < 64; j++) { S[j] = __expf(S[j] - mx); sum += S[j]; }
    const float inv = 1.f / sum;

    float* xo = g_xx[axis];
    #pragma unroll
    for (int d = 0; d < DV; d++) {
        float o = 0.f;
        #pragma unroll
        for (int j = 0; j < 64; j++) o += S[j] * vs[d][j];
        xo[(head * DV + d) * NAX + b * 64 + t] = o * inv;
    }
}

// ---------------------------------------------------------------------------
// K6b: depthwise 3x3 (SAME, zero pad) + affine + relu.  g1 -> g2
// ---------------------------------------------------------------------------
__global__ void dw_kernel(const float* __restrict__ wdw,
                          const float* __restrict__ sdw,
                          const float* __restrict__ bdw)
{
    const long long idx = (long long)blockIdx.x * blockDim.x + threadIdx.x;
    if (idx >= (long long)CDIM * NPIX) return;
    const int n = (int)(idx & (NPIX - 1));
    const int c = (int)(idx >> 16);
    const int b = n >> 12, hw = n & 4095;
    const int h = hw >> 6, w = hw & 63;
    const float* base = g_g1 + (size_t)c * NPIX + (size_t)b * 4096;
    const float* wk = wdw + c * 9;

    float acc = 0.f;
    #pragma unroll
    for (int dy = 0; dy < 3; dy++) {
        const int hh = h + dy - 1;
        if (hh < 0 || hh > 63) continue;
        #pragma unroll
        for (int dx = 0; dx < 3; dx++) {
            const int ww = w + dx - 1;
            if (ww < 0 || ww > 63) continue;
            acc += base[hh * 64 + ww] * wk[dy * 3 + dx];
        }
    }
    float v = acc * sdw[c] + bdw[c];
    g_g2[idx] = fmaxf(v, 0.f);
}

// ---------------------------------------------------------------------------
// Host launcher. Two-stream fork/join: the gate chain (K5g -> dw) depends
// only on x, so it runs on s2 concurrently with the attention chain.
// Stream/events are created once on the (uncaptured) correctness call and
// reused during graph capture (capture fork/join via events).
// ---------------------------------------------------------------------------
extern "C" void kernel_launch(void* const* d_in, const int* in_sizes, int n_in,
                              void* d_out, int out_size)
{
    const float* x        = (const float*)d_in[0];
    const float* wq       = (const float*)d_in[1];
    const float* sq       = (const float*)d_in[2];
    const float* bq       = (const float*)d_in[3];
    const float* wk       = (const float*)d_in[4];
    const float* sk       = (const float*)d_in[5];
    const float* bk       = (const float*)d_in[6];
    const float* wv       = (const float*)d_in[7];
    const float* sv       = (const float*)d_in[8];
    const float* bv       = (const float*)d_in[9];
    const float* pos_rowq = (const float*)d_in[10];
    const float* pos_rowk = (const float*)d_in[11];
    const float* pos_colq = (const float*)d_in[12];
    const float* pos_colk = (const float*)d_in[13];
    const float* w_row    = (const float*)d_in[14];
    const float* s_row    = (const float*)d_in[15];
    const float* b_row    = (const float*)d_in[16];
    const float* w_col    = (const float*)d_in[17];
    const float* s_col    = (const float*)d_in[18];
    const float* b_col    = (const float*)d_in[19];
    const float* w_proj   = (const float*)d_in[20];
    const float* s_proj   = (const float*)d_in[21];
    const float* b_proj   = (const float*)d_in[22];
    const float* w_sc     = (const float*)d_in[23];
    const float* s_sc     = (const float*)d_in[24];
    const float* b_sc     = (const float*)d_in[25];
    const float* w_dw     = (const float*)d_in[26];
    const float* s_dw     = (const float*)d_in[27];
    const float* b_dw     = (const float*)d_in[28];
    const float* w_pw     = (const float*)d_in[29];
    const float* s_pw     = (const float*)d_in[30];
    const float* b_pw     = (const float*)d_in[31];

    float *p_xm, *p_qe, *p_ke, *p_ve, *p_xx, *p_rout, *p_A, *p_g1, *p_g2, *p_P;
    cudaGetSymbolAddress((void**)&p_xm,   g_xmean);
    cudaGetSymbolAddress((void**)&p_qe,   g_qe);
    cudaGetSymbolAddress((void**)&p_ke,   g_ke);
    cudaGetSymbolAddress((void**)&p_ve,   g_ve);
    cudaGetSymbolAddress((void**)&p_xx,   g_xx);
    cudaGetSymbolAddress((void**)&p_rout, g_rout);
    cudaGetSymbolAddress((void**)&p_A,    g_A);
    cudaGetSymbolAddress((void**)&p_g1,   g_g1);
    cudaGetSymbolAddress((void**)&p_g2,   g_g2);
    cudaGetSymbolAddress((void**)&p_P,    g_P);

    static cudaStream_t s2 = nullptr;
    static cudaEvent_t evFork = nullptr, evJoin = nullptr;
    static int init_done = 0;
    if (!init_done) {
        cudaFuncSetAttribute(tc_gemm<0>, cudaFuncAttributeMaxDynamicSharedMemorySize, SMEM_SZ);
        cudaFuncSetAttribute(tc_gemm<2>, cudaFuncAttributeMaxDynamicSharedMemorySize, SMEM_SZ);
        cudaFuncSetAttribute(tc_gemm<3>, cudaFuncAttributeMaxDynamicSharedMemorySize, SMEM_SZ);
        cudaFuncSetAttribute(tc_gemm<4>, cudaFuncAttributeMaxDynamicSharedMemorySize, SMEM_SZ);
        cudaFuncSetAttribute(tc_gemm_qkv, cudaFuncAttributeMaxDynamicSharedMemorySize, SMEM_SZ);
        cudaFuncSetAttribute(tc_gemm_rowcol, cudaFuncAttributeMaxDynamicSharedMemorySize, SMEM_SZ);
        cudaStreamCreateWithFlags(&s2, cudaStreamNonBlocking);
        cudaEventCreateWithFlags(&evFork, cudaEventDisableTiming);
        cudaEventCreateWithFlags(&evJoin, cudaEventDisableTiming);
        init_done = 1;
    }

    // ---- fork: gate chain on s2 (depends only on x) ----
    cudaEventRecord(evFork, 0);
    cudaStreamWaitEvent(s2, evFork, 0);

    // K5g: g1 = cbn(x, w_sc)
    tc_gemm<3><<<dim3(2, 512), 256, SMEM_SZ, s2>>>(
        w_sc, x, s_sc, b_sc, p_g1, CDIM, nullptr, nullptr);
    // K6b: depthwise 3x3 + affine + relu
    dw_kernel<<<(CDIM * NPIX) / 256, 256, 0, s2>>>(w_dw, s_dw, b_dw);
    cudaEventRecord(evJoin, s2);

    // ---- main chain on default stream ----
    // K1: means (both axes into one [256][2048] buffer)
    mean_kernel<<<BB * CDIM, 64>>>(x);

    // K2: q/k/v projections, single batched launch (z = q,k,v)
    tc_gemm_qkv<<<dim3(4, NAX2 / 128, 3), 256, SMEM_SZ>>>(
        wq, sq, bq, p_qe, wk, sk, bk, p_ke, wv, sv, bv, p_ve, p_xm);

    // K3: axial attention (both axes)
    attn_kernel<<<2 * BB * NHEADS, 64>>>(pos_rowq, pos_rowk, pos_colq, pos_colk);

    // K4: w_row / w_col cbn on relu(xx), single batched launch
    tc_gemm_rowcol<<<dim3(DHD / 128, NAX / 128, 2), 256, SMEM_SZ>>>(
        w_row, s_row, b_row, w_col, s_col, b_col, p_xx, p_rout);

    // K5: A = relu(v + row + col)   (big GEMM over all pixels)
    tc_gemm<2><<<dim3(4, 512), 256, SMEM_SZ>>>(
        wv, x, sv, bv, p_A, CDIM, p_rout, p_rout + (size_t)DHD * NAX);

    // K6a: P = cbn(A, w_proj)
    tc_gemm<0><<<dim3(2, 512), 256, SMEM_SZ>>>(
        w_proj, p_A, s_proj, b_proj, p_P, DHD, nullptr, nullptr);

    // ---- join: K6c needs g2 (s2) and P (stream 0) ----
    cudaStreamWaitEvent(0, evJoin, 0);

    // K6c: out = h_sigmoid(cbn(g2, w_pw)) * P  (scatter to NCHW)
    tc_gemm<4><<<dim3(2, 512), 256, SMEM_SZ>>>(
        w_pw, p_g2, s_pw, b_pw, (float*)d_out, CDIM, p_P, nullptr);
}

// round 15
// speedup vs baseline: 3.1934x; 1.2353x over previous
#include <cuda_runtime.h>
#include <cstdint>
#include <cstddef>

// ---------------------------------------------------------------------------
// Problem constants
// ---------------------------------------------------------------------------
#define BB     16
#define CDIM   256
#define HDIM   64
#define WDIM   64
#define NHKD   128
#define DHD    512
#define NPIX   65536        // BB*HDIM*WDIM
#define NAX    1024         // BB*64
#define NAX2   2048         // both axes packed
#define NHEADS 8
#define KEYD   16
#define DV     64
#define ATTN_SCALE 0.25f

#define A_STRIDE 20         // floats per A smem row (16 data + 4 pad)
#define B_STRIDE 136        // floats per B smem row (128 data + 8 pad)
#define A_STAGE  (128 * A_STRIDE)
#define B_STAGE  (16 * B_STRIDE)
#define NSTAGE   4
#define SMEM_SZ  (NSTAGE * (A_STAGE + B_STAGE) * 4)   // 75776 bytes

// ---------------------------------------------------------------------------
// Scratch (device globals; no allocation allowed)
// ---------------------------------------------------------------------------
__device__ float g_xmean[CDIM * NAX2];         // [c][axis*1024 + b*64 + p]
__device__ float g_qe[NHKD * NAX2];
__device__ float g_ke[NHKD * NAX2];
__device__ float g_ve[DHD * NAX2];
__device__ float g_xx[2][DHD * NAX];           // attention output (pre-relu)
__device__ float g_rout[2][DHD * NAX];         // after w_row / w_col cbn
__device__ float g_A[(size_t)DHD * NPIX];      // relu(v + row + col), packed [m][n]
__device__ float g_g1[(size_t)CDIM * NPIX];    // gate after w_sc cbn, packed [c][n]
__device__ float g_g2[(size_t)CDIM * NPIX];    // relu(dw(g1)), packed [c][n]
__device__ float g_P[(size_t)CDIM * NPIX];     // proj output, packed [m][n]

// ---------------------------------------------------------------------------
// PTX helpers
// ---------------------------------------------------------------------------
__device__ __forceinline__ void mma_tf32(float* c, const uint32_t* a,
                                         const uint32_t* b)
{
    asm volatile(
        "mma.sync.aligned.m16n8k8.row.col.f32.tf32.tf32.f32 "
        "{%0,%1,%2,%3}, {%4,%5,%6,%7}, {%8,%9}, {%0,%1,%2,%3};"
        : "+f"(c[0]), "+f"(c[1]), "+f"(c[2]), "+f"(c[3])
        : "r"(a[0]), "r"(a[1]), "r"(a[2]), "r"(a[3]),
          "r"(b[0]), "r"(b[1]));
}

__device__ __forceinline__ uint32_t tf32_rna(float x)
{
    uint32_t r;
    asm("cvt.rna.tf32.f32 %0, %1;" : "=r"(r) : "f"(x));
    return r;
}

__device__ __forceinline__ void tf32_split(float x, uint32_t& hi, uint32_t& lo)
{
    hi = tf32_rna(x);
    lo = __float_as_uint(x - __uint_as_float(hi));
}

__device__ __forceinline__ void cp16(void* dst_smem, const void* src)
{
    uint32_t d = (uint32_t)__cvta_generic_to_shared(dst_smem);
    asm volatile("cp.async.cg.shared.global [%0], [%1], 16;"
                 :: "r"(d), "l"(src));
}
#define CP_COMMIT() asm volatile("cp.async.commit_group;" ::: "memory")
#define CP_WAIT3()  asm volatile("cp.async.wait_group 3;" ::: "memory")

// ---------------------------------------------------------------------------
// 2xTF32 GEMM core: out = epilogue( W[M,K] @ X[K,N] ).
// A split hi(rna)+lo; B rounded to hi(rna) only.
// D = Ahi*Bhi + Alo*Bhi. Dropped Ahi*Blo term is an unbiased ~2^-12 residual
// -> sqrt(K) cancellation -> expected rel_err ~1e-4 (vs 1e-3 gate).
// CTA tile 128(M) x 128(N); K-chunk 16; cp.async 4-stage pipeline.
// 256 threads = 8 warps (2x4); warp tile 64x32.
// MODE 0: X packed,           out = acc*s+b                        (packed)
// MODE 1: X packed + relu-in, out = acc*s+b                        (packed)
// MODE 2: X = x (BCHW, K=256) out = relu(acc*s+b + e0[h] + e1[w])  (packed)
// MODE 3: X = x (BCHW, K=256) out = acc*s+b                        (packed)
// MODE 4: X packed,           out = h_sigmoid(acc*s+b) * e0, scatter to BCHW
// ---------------------------------------------------------------------------
template <int MODE>
__device__ __forceinline__ void gemm_core(
    const float* __restrict__ Wm, const float* __restrict__ X,
    const float* __restrict__ scale, const float* __restrict__ bias,
    float* __restrict__ out, int K,
    const float* __restrict__ e0, const float* __restrict__ e1,
    int bm, int bn, int Nld, float* As, float* Bs)
{
    const int t = threadIdx.x;         // 256
    const int warp = t >> 5, lane = t & 31;
    const int wm = (warp >> 2) * 64;   // 0 | 64
    const int wn = (warp & 3) * 32;    // 0..96
    const int gid = lane >> 2;         // 0..7
    const int tig = lane & 3;          // 0..3

    const int mA = t >> 1;             // 0..127
    const int kq = (t & 1) * 8;        // 0 | 8

    float acc[4][4][4];
    #pragma unroll
    for (int i = 0; i < 4; i++)
        #pragma unroll
        for (int j = 0; j < 4; j++)
            #pragma unroll
            for (int r = 0; r < 4; r++) acc[i][j][r] = 0.f;

    const int NC = K >> 4;

    // stage issue: chunk c -> buffer c % NSTAGE
    auto issue = [&](int c) {
        const int st = c % NSTAGE;
        const int k0 = c << 4;
        const float* wsrc = &Wm[(size_t)(bm + mA) * K + k0 + kq];
        float* ad = As + st * A_STAGE + mA * A_STRIDE + kq;
        cp16(ad, wsrc);
        cp16(ad + 4, wsrc + 4);
        #pragma unroll
        for (int j = 0; j < 2; j++) {
            const int idx = t + j * 256;
            const int kk = idx >> 5, nf = idx & 31;
            const int kg = k0 + kk;
            const float* src;
            if (MODE == 2 || MODE == 3) {
                const int n = bn + nf * 4;
                const int b = n >> 12, hw = n & 4095;
                src = &X[((size_t)b * CDIM + kg) * 4096 + hw];
            } else {
                src = &X[(size_t)kg * Nld + bn + nf * 4];
            }
            cp16(Bs + st * B_STAGE + kk * B_STRIDE + nf * 4, src);
        }
    };

    issue(0); CP_COMMIT();
    if (NC > 1) issue(1);
    CP_COMMIT();
    if (NC > 2) issue(2);
    CP_COMMIT();

    for (int c = 0; c < NC; c++) {
        if (c + 3 < NC) issue(c + 3);
        CP_COMMIT();
        CP_WAIT3();                    // chunk c landed (<=3 newer outstanding)
        __syncthreads();

        const int st = c % NSTAGE;
        const float* Ab = As + st * A_STAGE;
        const float* Bb = Bs + st * B_STAGE;

        #pragma unroll
        for (int ks = 0; ks < 2; ks++) {
            const int kb = ks * 8;

            // B fragments: hi (rna) only
            uint32_t bhi[4][2];
            #pragma unroll
            for (int nt = 0; nt < 4; nt++) {
                const int col = wn + nt * 8 + gid;
                float b0 = Bb[(kb + tig) * B_STRIDE + col];
                float b1 = Bb[(kb + tig + 4) * B_STRIDE + col];
                if (MODE == 1) { b0 = fmaxf(b0, 0.f); b1 = fmaxf(b1, 0.f); }
                bhi[nt][0] = tf32_rna(b0);
                bhi[nt][1] = tf32_rna(b1);
            }

            #pragma unroll
            for (int mg = 0; mg < 2; mg++) {       // mt pairs {0,1}, {2,3}
                uint32_t ahi[2][4], alo[2][4];
                #pragma unroll
                for (int m2 = 0; m2 < 2; m2++) {
                    const int row = wm + (mg * 2 + m2) * 16 + gid;
                    tf32_split(Ab[row * A_STRIDE + kb + tig],           ahi[m2][0], alo[m2][0]);
                    tf32_split(Ab[(row + 8) * A_STRIDE + kb + tig],     ahi[m2][1], alo[m2][1]);
                    tf32_split(Ab[row * A_STRIDE + kb + tig + 4],       ahi[m2][2], alo[m2][2]);
                    tf32_split(Ab[(row + 8) * A_STRIDE + kb + tig + 4], ahi[m2][3], alo[m2][3]);
                }
                // pass-major: each acc reused only every 8 MMAs
                #pragma unroll
                for (int m2 = 0; m2 < 2; m2++)
                    #pragma unroll
                    for (int nt = 0; nt < 4; nt++)
                        mma_tf32(acc[mg * 2 + m2][nt], ahi[m2], bhi[nt]);
                #pragma unroll
                for (int m2 = 0; m2 < 2; m2++)
                    #pragma unroll
                    for (int nt = 0; nt < 4; nt++)
                        mma_tf32(acc[mg * 2 + m2][nt], alo[m2], bhi[nt]);
            }
        }
        __syncthreads();               // done reading stage before overwrite
    }

    // --- epilogue ---
    #pragma unroll
    for (int mt = 0; mt < 4; mt++) {
        const int r0 = bm + wm + mt * 16 + gid;
        const int r1 = r0 + 8;
        const float s0 = scale[r0], bi0 = bias[r0];
        const float s1 = scale[r1], bi1 = bias[r1];
        #pragma unroll
        for (int nt = 0; nt < 4; nt++) {
            const int n0 = bn + wn + nt * 8 + tig * 2;
            float v00 = acc[mt][nt][0] * s0 + bi0;
            float v01 = acc[mt][nt][1] * s0 + bi0;
            float v10 = acc[mt][nt][2] * s1 + bi1;
            float v11 = acc[mt][nt][3] * s1 + bi1;
            if (MODE == 2) {
                const int b = n0 >> 12, hw = n0 & 4095;
                const int h = hw >> 6, w = hw & 63;
                const int o = (b << 6);
                const float re0 = e0[r0 * NAX + o + h];
                const float re1 = e0[r1 * NAX + o + h];
                const float c0a = e1[r0 * NAX + o + w];
                const float c0b = e1[r0 * NAX + o + w + 1];
                const float c1a = e1[r1 * NAX + o + w];
                const float c1b = e1[r1 * NAX + o + w + 1];
                float2 u0, u1;
                u0.x = fmaxf(v00 + re0 + c0a, 0.f);
                u0.y = fmaxf(v01 + re0 + c0b, 0.f);
                u1.x = fmaxf(v10 + re1 + c1a, 0.f);
                u1.y = fmaxf(v11 + re1 + c1b, 0.f);
                *reinterpret_cast<float2*>(&out[(size_t)r0 * Nld + n0]) = u0;
                *reinterpret_cast<float2*>(&out[(size_t)r1 * Nld + n0]) = u1;
            } else if (MODE == 4) {
                const int b = n0 >> 12, hw = n0 & 4095;
                float2 p0 = *reinterpret_cast<const float2*>(&e0[(size_t)r0 * Nld + n0]);
                float2 p1 = *reinterpret_cast<const float2*>(&e0[(size_t)r1 * Nld + n0]);
                float2 u0, u1;
                u0.x = fminf(fmaxf(v00 + 3.f, 0.f), 6.f) * (1.f / 6.f) * p0.x;
                u0.y = fminf(fmaxf(v01 + 3.f, 0.f), 6.f) * (1.f / 6.f) * p0.y;
                u1.x = fminf(fmaxf(v10 + 3.f, 0.f), 6.f) * (1.f / 6.f) * p1.x;
                u1.y = fminf(fmaxf(v11 + 3.f, 0.f), 6.f) * (1.f / 6.f) * p1.y;
                *reinterpret_cast<float2*>(
                    &out[((size_t)b * CDIM + r0) * 4096 + hw]) = u0;
                *reinterpret_cast<float2*>(
                    &out[((size_t)b * CDIM + r1) * 4096 + hw]) = u1;
            } else {
                float2 u0, u1;
                u0.x = v00; u0.y = v01;
                u1.x = v10; u1.y = v11;
                *reinterpret_cast<float2*>(&out[(size_t)r0 * Nld + n0]) = u0;
                *reinterpret_cast<float2*>(&out[(size_t)r1 * Nld + n0]) = u1;
            }
        }
    }
}

// ---------------------------------------------------------------------------
// GEMM kernel wrappers (dynamic smem, 4 stages)
// Grid layout: (x = M-blocks, y = N-blocks) so CTAs sharing an N-slab of X
// are launch-adjacent -> X slab read hits L2 for all but the first.
// ---------------------------------------------------------------------------
template <int MODE>
__global__ void __launch_bounds__(256, 2)
tc_gemm(const float* __restrict__ Wm, const float* __restrict__ X,
        const float* __restrict__ scale, const float* __restrict__ bias,
        float* __restrict__ out, int K,
        const float* __restrict__ e0, const float* __restrict__ e1)
{
    extern __shared__ float dsm[];
    gemm_core<MODE>(Wm, X, scale, bias, out, K, e0, e1,
                    blockIdx.x * 128, blockIdx.y * 128, gridDim.y * 128,
                    dsm, dsm + NSTAGE * A_STAGE);
}

// batched q/k/v projection: z=0 -> q (M=128), z=1 -> k (M=128), z=2 -> v (M=512)
__global__ void __launch_bounds__(256, 2)
tc_gemm_qkv(const float* __restrict__ wq, const float* __restrict__ sq,
            const float* __restrict__ bq, float* __restrict__ oq,
            const float* __restrict__ wk, const float* __restrict__ sk,
            const float* __restrict__ bk, float* __restrict__ ok,
            const float* __restrict__ wv, const float* __restrict__ sv,
            const float* __restrict__ bv, float* __restrict__ ov,
            const float* __restrict__ X)
{
    extern __shared__ float dsm[];
    const int z = blockIdx.z;
    const int xv = (z < 2) ? 1 : 4;    // m-blocks valid for this z
    if ((int)blockIdx.x >= xv) return;
    const float* W = (z == 0) ? wq : (z == 1) ? wk : wv;
    const float* s = (z == 0) ? sq : (z == 1) ? sk : sv;
    const float* b = (z == 0) ? bq : (z == 1) ? bk : bv;
    float*       o = (z == 0) ? oq : (z == 1) ? ok : ov;
    gemm_core<0>(W, X, s, b, o, CDIM, nullptr, nullptr,
                 blockIdx.x * 128, blockIdx.y * 128, NAX2,
                 dsm, dsm + NSTAGE * A_STAGE);
}

// batched row/col cbn: z selects weight set + xx/rout slab
__global__ void __launch_bounds__(256, 2)
tc_gemm_rowcol(const float* __restrict__ w_row, const float* __restrict__ s_row,
               const float* __restrict__ b_row,
               const float* __restrict__ w_col, const float* __restrict__ s_col,
               const float* __restrict__ b_col,
               const float* __restrict__ xx, float* __restrict__ rout)
{
    extern __shared__ float dsm[];
    const int z = blockIdx.z;
    const float* W = z ? w_col : w_row;
    const float* s = z ? s_col : s_row;
    const float* b = z ? b_col : b_row;
    const float* X = xx + (size_t)z * DHD * NAX;
    float*       o = rout + (size_t)z * DHD * NAX;
    gemm_core<1>(W, X, s, b, o, DHD, nullptr, nullptr,
                 blockIdx.x * 128, blockIdx.y * 128, NAX,
                 dsm, dsm + NSTAGE * A_STAGE);
}

// ---------------------------------------------------------------------------
// K1: row/col means of x -> packed [256][2048] (axis 0 = row, axis 1 = col)
// ---------------------------------------------------------------------------
__global__ void mean_kernel(const float* __restrict__ x)
{
    __shared__ float s[64 * 65];
    const int blk = blockIdx.x;                // b*256 + c
    const float* base = x + (size_t)blk * 4096;
    const int t = threadIdx.x;                 // 64 threads

    #pragma unroll
    for (int i = 0; i < 64; i++) s[i * 65 + t] = base[i * 64 + t];
    __syncthreads();

    float rs = 0.f, cs = 0.f;
    #pragma unroll
    for (int i = 0; i < 64; i++) {
        rs += s[t * 65 + i];
        cs += s[i * 65 + t];
    }
    const int b = blk >> 8;
    const int c = blk & 255;
    g_xmean[c * NAX2 + b * 64 + t]        = rs * (1.f / 64.f);
    g_xmean[c * NAX2 + 1024 + b * 64 + t] = cs * (1.f / 64.f);
}

// ---------------------------------------------------------------------------
// K3: axial attention. One block per (axis, b, head); 64 threads.
// ---------------------------------------------------------------------------
__device__ __forceinline__ float pos_interp(const float* __restrict__ p,
                                            int ch, int i)
{
    float c = (i + 0.5f) * 0.25f - 0.5f;
    c = fminf(fmaxf(c, 0.f), 15.f);
    int lo = (int)floorf(c);
    int hi = min(lo + 1, 15);
    float tt = c - (float)lo;
    const float* row = p + ch * 16;
    return row[lo] * (1.f - tt) + row[hi] * tt;
}

__global__ void attn_kernel(const float* __restrict__ pos_rowq,
                            const float* __restrict__ pos_rowk,
                            const float* __restrict__ pos_colq,
                            const float* __restrict__ pos_colk)
{
    const int blk  = blockIdx.x;          // axis*128 + b*8 + head
    const int axis = blk >> 7;
    const int b    = (blk >> 3) & 15;
    const int head = blk & 7;
    const float* pq = axis ? pos_colq : pos_rowq;
    const float* pk = axis ? pos_colk : pos_rowk;
    const int col0 = axis * 1024 + b * 64;

    __shared__ float ks[KEYD][64];
    __shared__ float vs[DV][64];
    const int t = threadIdx.x;            // 64

    float qr[KEYD];
    #pragma unroll
    for (int c = 0; c < KEYD; c++) {
        const int ch = head * KEYD + c;
        ks[c][t] = g_ke[ch * NAX2 + col0 + t] + pos_interp(pk, ch, t);
        qr[c]    = g_qe[ch * NAX2 + col0 + t] + pos_interp(pq, ch, t);
    }
    #pragma unroll
    for (int d = 0; d < DV; d++)
        vs[d][t] = g_ve[(head * DV + d) * NAX2 + col0 + t];
    __syncthreads();

    float S[64];
    float mx = -1e30f;
    #pragma unroll
    for (int j = 0; j < 64; j++) {
        float s = 0.f;
        #pragma unroll
        for (int c = 0; c < KEYD; c++) s += qr[c] * ks[c][j];
        s *= ATTN_SCALE;
        S[j] = s;
        mx = fmaxf(mx, s);
    }
    float sum = 0.f;
    #pragma unroll
    for (int j = 0; j < 64; j++) { S[j] = __expf(S[j] - mx); sum += S[j]; }
    const float inv = 1.f / sum;

    float* xo = g_xx[axis];
    #pragma unroll
    for (int d = 0; d < DV; d++) {
        float o = 0.f;
        #pragma unroll
        for (int j = 0; j < 64; j++) o += S[j] * vs[d][j];
        xo[(head * DV + d) * NAX + b * 64 + t] = o * inv;
    }
}

// ---------------------------------------------------------------------------
// K6b: depthwise 3x3 (SAME, zero pad) + affine + relu.  g1 -> g2
// ---------------------------------------------------------------------------
__global__ void dw_kernel(const float* __restrict__ wdw,
                          const float* __restrict__ sdw,
                          const float* __restrict__ bdw)
{
    const long long idx = (long long)blockIdx.x * blockDim.x + threadIdx.x;
    if (idx >= (long long)CDIM * NPIX) return;
    const int n = (int)(idx & (NPIX - 1));
    const int c = (int)(idx >> 16);
    const int b = n >> 12, hw = n & 4095;
    const int h = hw >> 6, w = hw & 63;
    const float* base = g_g1 + (size_t)c * NPIX + (size_t)b * 4096;
    const float* wk = wdw + c * 9;

    float acc = 0.f;
    #pragma unroll
    for (int dy = 0; dy < 3; dy++) {
        const int hh = h + dy - 1;
        if (hh < 0 || hh > 63) continue;
        #pragma unroll
        for (int dx = 0; dx < 3; dx++) {
            const int ww = w + dx - 1;
            if (ww < 0 || ww > 63) continue;
            acc += base[hh * 64 + ww] * wk[dy * 3 + dx];
        }
    }
    float v = acc * sdw[c] + bdw[c];
    g_g2[idx] = fmaxf(v, 0.f);
}

// ---------------------------------------------------------------------------
// Host launcher. Two-stream fork/join: the gate chain (K5g -> dw) depends
// only on x, so it runs on s2 concurrently with the attention chain.
// ---------------------------------------------------------------------------
extern "C" void kernel_launch(void* const* d_in, const int* in_sizes, int n_in,
                              void* d_out, int out_size)
{
    const float* x        = (const float*)d_in[0];
    const float* wq       = (const float*)d_in[1];
    const float* sq       = (const float*)d_in[2];
    const float* bq       = (const float*)d_in[3];
    const float* wk       = (const float*)d_in[4];
    const float* sk       = (const float*)d_in[5];
    const float* bk       = (const float*)d_in[6];
    const float* wv       = (const float*)d_in[7];
    const float* sv       = (const float*)d_in[8];
    const float* bv       = (const float*)d_in[9];
    const float* pos_rowq = (const float*)d_in[10];
    const float* pos_rowk = (const float*)d_in[11];
    const float* pos_colq = (const float*)d_in[12];
    const float* pos_colk = (const float*)d_in[13];
    const float* w_row    = (const float*)d_in[14];
    const float* s_row    = (const float*)d_in[15];
    const float* b_row    = (const float*)d_in[16];
    const float* w_col    = (const float*)d_in[17];
    const float* s_col    = (const float*)d_in[18];
    const float* b_col    = (const float*)d_in[19];
    const float* w_proj   = (const float*)d_in[20];
    const float* s_proj   = (const float*)d_in[21];
    const float* b_proj   = (const float*)d_in[22];
    const float* w_sc     = (const float*)d_in[23];
    const float* s_sc     = (const float*)d_in[24];
    const float* b_sc     = (const float*)d_in[25];
    const float* w_dw     = (const float*)d_in[26];
    const float* s_dw     = (const float*)d_in[27];
    const float* b_dw     = (const float*)d_in[28];
    const float* w_pw     = (const float*)d_in[29];
    const float* s_pw     = (const float*)d_in[30];
    const float* b_pw     = (const float*)d_in[31];

    float *p_xm, *p_qe, *p_ke, *p_ve, *p_xx, *p_rout, *p_A, *p_g1, *p_g2, *p_P;
    cudaGetSymbolAddress((void**)&p_xm,   g_xmean);
    cudaGetSymbolAddress((void**)&p_qe,   g_qe);
    cudaGetSymbolAddress((void**)&p_ke,   g_ke);
    cudaGetSymbolAddress((void**)&p_ve,   g_ve);
    cudaGetSymbolAddress((void**)&p_xx,   g_xx);
    cudaGetSymbolAddress((void**)&p_rout, g_rout);
    cudaGetSymbolAddress((void**)&p_A,    g_A);
    cudaGetSymbolAddress((void**)&p_g1,   g_g1);
    cudaGetSymbolAddress((void**)&p_g2,   g_g2);
    cudaGetSymbolAddress((void**)&p_P,    g_P);

    static cudaStream_t s2 = nullptr;
    static cudaEvent_t evFork = nullptr, evJoin = nullptr;
    static int init_done = 0;
    if (!init_done) {
        cudaFuncSetAttribute(tc_gemm<0>, cudaFuncAttributeMaxDynamicSharedMemorySize, SMEM_SZ);
        cudaFuncSetAttribute(tc_gemm<2>, cudaFuncAttributeMaxDynamicSharedMemorySize, SMEM_SZ);
        cudaFuncSetAttribute(tc_gemm<3>, cudaFuncAttributeMaxDynamicSharedMemorySize, SMEM_SZ);
        cudaFuncSetAttribute(tc_gemm<4>, cudaFuncAttributeMaxDynamicSharedMemorySize, SMEM_SZ);
        cudaFuncSetAttribute(tc_gemm_qkv, cudaFuncAttributeMaxDynamicSharedMemorySize, SMEM_SZ);
        cudaFuncSetAttribute(tc_gemm_rowcol, cudaFuncAttributeMaxDynamicSharedMemorySize, SMEM_SZ);
        cudaStreamCreateWithFlags(&s2, cudaStreamNonBlocking);
        cudaEventCreateWithFlags(&evFork, cudaEventDisableTiming);
        cudaEventCreateWithFlags(&evJoin, cudaEventDisableTiming);
        init_done = 1;
    }

    // ---- fork: gate chain on s2 (depends only on x) ----
    cudaEventRecord(evFork, 0);
    cudaStreamWaitEvent(s2, evFork, 0);

    // K5g: g1 = cbn(x, w_sc)
    tc_gemm<3><<<dim3(2, 512), 256, SMEM_SZ, s2>>>(
        w_sc, x, s_sc, b_sc, p_g1, CDIM, nullptr, nullptr);
    // K6b: depthwise 3x3 + affine + relu
    dw_kernel<<<(CDIM * NPIX) / 256, 256, 0, s2>>>(w_dw, s_dw, b_dw);
    cudaEventRecord(evJoin, s2);

    // ---- main chain on default stream ----
    // K1: means (both axes into one [256][2048] buffer)
    mean_kernel<<<BB * CDIM, 64>>>(x);

    // K2: q/k/v projections, single batched launch (z = q,k,v)
    tc_gemm_qkv<<<dim3(4, NAX2 / 128, 3), 256, SMEM_SZ>>>(
        wq, sq, bq, p_qe, wk, sk, bk, p_ke, wv, sv, bv, p_ve, p_xm);

    // K3: axial attention (both axes)
    attn_kernel<<<2 * BB * NHEADS, 64>>>(pos_rowq, pos_rowk, pos_colq, pos_colk);

    // K4: w_row / w_col cbn on relu(xx), single batched launch
    tc_gemm_rowcol<<<dim3(DHD / 128, NAX / 128, 2), 256, SMEM_SZ>>>(
        w_row, s_row, b_row, w_col, s_col, b_col, p_xx, p_rout);

    // K5: A = relu(v + row + col)   (big GEMM over all pixels)
    tc_gemm<2><<<dim3(4, 512), 256, SMEM_SZ>>>(
        wv, x, sv, bv, p_A, CDIM, p_rout, p_rout + (size_t)DHD * NAX);

    // K6a: P = cbn(A, w_proj)
    tc_gemm<0><<<dim3(2, 512), 256, SMEM_SZ>>>(
        w_proj, p_A, s_proj, b_proj, p_P, DHD, nullptr, nullptr);

    // ---- join: K6c needs g2 (s2) and P (stream 0) ----
    cudaStreamWaitEvent(0, evJoin, 0);

    // K6c: out = h_sigmoid(cbn(g2, w_pw)) * P  (scatter to NCHW)
    tc_gemm<4><<<dim3(2, 512), 256, SMEM_SZ>>>(
        w_pw, p_g2, s_pw, b_pw, (float*)d_out, CDIM, p_P, nullptr);
}

// round 17
// speedup vs baseline: 4.2888x; 1.3430x over previous
#include <cuda_runtime.h>
#include <cstdint>
#include <cstddef>

// ---------------------------------------------------------------------------
// Problem constants
// ---------------------------------------------------------------------------
#define BB     16
#define CDIM   256
#define HDIM   64
#define WDIM   64
#define NHKD   128
#define DHD    512
#define NPIX   65536        // BB*HDIM*WDIM
#define NAX    1024         // BB*64
#define NAX2   2048         // both axes packed
#define NHEADS 8
#define KEYD   16
#define DV     64
#define ATTN_SCALE 0.25f

#define A_STRIDE 20         // floats per A smem row (16 data + 4 pad)
#define B_STRIDE 136        // floats per B smem row (128 data + 8 pad)
#define A_STAGE  (128 * A_STRIDE)
#define B_STAGE  (16 * B_STRIDE)
#define NSTAGE   4
#define SMEM_SZ  (NSTAGE * (A_STAGE + B_STAGE) * 4)   // 75776 bytes

// ---------------------------------------------------------------------------
// Scratch (device globals; no allocation allowed)
// ---------------------------------------------------------------------------
__device__ float g_xmean[CDIM * NAX2];         // [c][axis*1024 + b*64 + p]
__device__ float g_qe[NHKD * NAX2];
__device__ float g_ke[NHKD * NAX2];
__device__ float g_ve[DHD * NAX2];
__device__ float g_xx[2][DHD * NAX];           // attention output (pre-relu)
__device__ float g_rout[2][DHD * NAX];         // after w_row / w_col cbn
__device__ float g_A[(size_t)DHD * NPIX];      // relu(v + row + col), packed [m][n]
__device__ float g_g1[(size_t)CDIM * NPIX];    // gate after w_sc cbn, packed [c][n]
__device__ float g_g2[(size_t)CDIM * NPIX];    // relu(dw(g1)), packed [c][n]
__device__ float g_P[(size_t)CDIM * NPIX];     // proj output, packed [m][n]

// ---------------------------------------------------------------------------
// PTX helpers
// ---------------------------------------------------------------------------
__device__ __forceinline__ void mma_tf32(float* c, const uint32_t* a,
                                         const uint32_t* b)
{
    asm volatile(
        "mma.sync.aligned.m16n8k8.row.col.f32.tf32.tf32.f32 "
        "{%0,%1,%2,%3}, {%4,%5,%6,%7}, {%8,%9}, {%0,%1,%2,%3};"
        : "+f"(c[0]), "+f"(c[1]), "+f"(c[2]), "+f"(c[3])
        : "r"(a[0]), "r"(a[1]), "r"(a[2]), "r"(a[3]),
          "r"(b[0]), "r"(b[1]));
}

__device__ __forceinline__ uint32_t tf32_rna(float x)
{
    uint32_t r;
    asm("cvt.rna.tf32.f32 %0, %1;" : "=r"(r) : "f"(x));
    return r;
}

__device__ __forceinline__ void cp16(void* dst_smem, const void* src)
{
    uint32_t d = (uint32_t)__cvta_generic_to_shared(dst_smem);
    asm volatile("cp.async.cg.shared.global [%0], [%1], 16;"
                 :: "r"(d), "l"(src));
}
#define CP_COMMIT() asm volatile("cp.async.commit_group;" ::: "memory")
#define CP_WAIT3()  asm volatile("cp.async.wait_group 3;" ::: "memory")

// ---------------------------------------------------------------------------
// 1xTF32(rna) GEMM core: out = epilogue( rna(W) @ rna(X) ).
// Both operands rounded to tf32 with round-to-nearest (NOT truncation —
// truncation's 0.5-ulp bias accumulates linearly in K and fails the 1e-3
// gate; rna errors are unbiased -> sqrt(K) cancellation).
// Measured calibration: A_exact * rna(B) (2x scheme) gave 2.97e-4; adding
// the independent rna(A) source predicts ~sqrt(2)*2.97e-4 ~ 4.2e-4.
// CTA tile 128(M) x 128(N); K-chunk 16; cp.async 4-stage pipeline.
// 256 threads = 8 warps (2x4); warp tile 64x32.
// MODE 0: X packed,           out = acc*s+b                        (packed)
// MODE 1: X packed + relu-in, out = acc*s+b                        (packed)
// MODE 2: X = x (BCHW, K=256) out = relu(acc*s+b + e0[h] + e1[w])  (packed)
// MODE 3: X = x (BCHW, K=256) out = acc*s+b                        (packed)
// MODE 4: X packed,           out = h_sigmoid(acc*s+b) * e0, scatter to BCHW
// ---------------------------------------------------------------------------
template <int MODE>
__device__ __forceinline__ void gemm_core(
    const float* __restrict__ Wm, const float* __restrict__ X,
    const float* __restrict__ scale, const float* __restrict__ bias,
    float* __restrict__ out, int K,
    const float* __restrict__ e0, const float* __restrict__ e1,
    int bm, int bn, int Nld, float* As, float* Bs)
{
    const int t = threadIdx.x;         // 256
    const int warp = t >> 5, lane = t & 31;
    const int wm = (warp >> 2) * 64;   // 0 | 64
    const int wn = (warp & 3) * 32;    // 0..96
    const int gid = lane >> 2;         // 0..7
    const int tig = lane & 3;          // 0..3

    const int mA = t >> 1;             // 0..127
    const int kq = (t & 1) * 8;        // 0 | 8

    float acc[4][4][4];
    #pragma unroll
    for (int i = 0; i < 4; i++)
        #pragma unroll
        for (int j = 0; j < 4; j++)
            #pragma unroll
            for (int r = 0; r < 4; r++) acc[i][j][r] = 0.f;

    const int NC = K >> 4;

    // stage issue: chunk c -> buffer c % NSTAGE
    auto issue = [&](int c) {
        const int st = c % NSTAGE;
        const int k0 = c << 4;
        const float* wsrc = &Wm[(size_t)(bm + mA) * K + k0 + kq];
        float* ad = As + st * A_STAGE + mA * A_STRIDE + kq;
        cp16(ad, wsrc);
        cp16(ad + 4, wsrc + 4);
        #pragma unroll
        for (int j = 0; j < 2; j++) {
            const int idx = t + j * 256;
            const int kk = idx >> 5, nf = idx & 31;
            const int kg = k0 + kk;
            const float* src;
            if (MODE == 2 || MODE == 3) {
                const int n = bn + nf * 4;
                const int b = n >> 12, hw = n & 4095;
                src = &X[((size_t)b * CDIM + kg) * 4096 + hw];
            } else {
                src = &X[(size_t)kg * Nld + bn + nf * 4];
            }
            cp16(Bs + st * B_STAGE + kk * B_STRIDE + nf * 4, src);
        }
    };

    issue(0); CP_COMMIT();
    if (NC > 1) issue(1);
    CP_COMMIT();
    if (NC > 2) issue(2);
    CP_COMMIT();

    for (int c = 0; c < NC; c++) {
        if (c + 3 < NC) issue(c + 3);
        CP_COMMIT();
        CP_WAIT3();                    // chunk c landed (<=3 newer outstanding)
        __syncthreads();

        const int st = c % NSTAGE;
        const float* Ab = As + st * A_STAGE;
        const float* Bb = Bs + st * B_STAGE;

        #pragma unroll
        for (int ks = 0; ks < 2; ks++) {
            const int kb = ks * 8;

            // B fragments: rna-rounded tf32
            uint32_t bhi[4][2];
            #pragma unroll
            for (int nt = 0; nt < 4; nt++) {
                const int col = wn + nt * 8 + gid;
                float b0 = Bb[(kb + tig) * B_STRIDE + col];
                float b1 = Bb[(kb + tig + 4) * B_STRIDE + col];
                if (MODE == 1) { b0 = fmaxf(b0, 0.f); b1 = fmaxf(b1, 0.f); }
                bhi[nt][0] = tf32_rna(b0);
                bhi[nt][1] = tf32_rna(b1);
            }

            #pragma unroll
            for (int mg = 0; mg < 2; mg++) {       // mt pairs {0,1}, {2,3}
                uint32_t ahi[2][4];
                #pragma unroll
                for (int m2 = 0; m2 < 2; m2++) {
                    const int row = wm + (mg * 2 + m2) * 16 + gid;
                    ahi[m2][0] = tf32_rna(Ab[row * A_STRIDE + kb + tig]);
                    ahi[m2][1] = tf32_rna(Ab[(row + 8) * A_STRIDE + kb + tig]);
                    ahi[m2][2] = tf32_rna(Ab[row * A_STRIDE + kb + tig + 4]);
                    ahi[m2][3] = tf32_rna(Ab[(row + 8) * A_STRIDE + kb + tig + 4]);
                }
                #pragma unroll
                for (int m2 = 0; m2 < 2; m2++)
                    #pragma unroll
                    for (int nt = 0; nt < 4; nt++)
                        mma_tf32(acc[mg * 2 + m2][nt], ahi[m2], bhi[nt]);
            }
        }
        __syncthreads();               // done reading stage before overwrite
    }

    // --- epilogue ---
    #pragma unroll
    for (int mt = 0; mt < 4; mt++) {
        const int r0 = bm + wm + mt * 16 + gid;
        const int r1 = r0 + 8;
        const float s0 = scale[r0], bi0 = bias[r0];
        const float s1 = scale[r1], bi1 = bias[r1];
        #pragma unroll
        for (int nt = 0; nt < 4; nt++) {
            const int n0 = bn + wn + nt * 8 + tig * 2;
            float v00 = acc[mt][nt][0] * s0 + bi0;
            float v01 = acc[mt][nt][1] * s0 + bi0;
            float v10 = acc[mt][nt][2] * s1 + bi1;
            float v11 = acc[mt][nt][3] * s1 + bi1;
            if (MODE == 2) {
                const int b = n0 >> 12, hw = n0 & 4095;
                const int h = hw >> 6, w = hw & 63;
                const int o = (b << 6);
                const float re0 = e0[r0 * NAX + o + h];
                const float re1 = e0[r1 * NAX + o + h];
                const float c0a = e1[r0 * NAX + o + w];
                const float c0b = e1[r0 * NAX + o + w + 1];
                const float c1a = e1[r1 * NAX + o + w];
                const float c1b = e1[r1 * NAX + o + w + 1];
                float2 u0, u1;
                u0.x = fmaxf(v00 + re0 + c0a, 0.f);
                u0.y = fmaxf(v01 + re0 + c0b, 0.f);
                u1.x = fmaxf(v10 + re1 + c1a, 0.f);
                u1.y = fmaxf(v11 + re1 + c1b, 0.f);
                *reinterpret_cast<float2*>(&out[(size_t)r0 * Nld + n0]) = u0;
                *reinterpret_cast<float2*>(&out[(size_t)r1 * Nld + n0]) = u1;
            } else if (MODE == 4) {
                const int b = n0 >> 12, hw = n0 & 4095;
                float2 p0 = *reinterpret_cast<const float2*>(&e0[(size_t)r0 * Nld + n0]);
                float2 p1 = *reinterpret_cast<const float2*>(&e0[(size_t)r1 * Nld + n0]);
                float2 u0, u1;
                u0.x = fminf(fmaxf(v00 + 3.f, 0.f), 6.f) * (1.f / 6.f) * p0.x;
                u0.y = fminf(fmaxf(v01 + 3.f, 0.f), 6.f) * (1.f / 6.f) * p0.y;
                u1.x = fminf(fmaxf(v10 + 3.f, 0.f), 6.f) * (1.f / 6.f) * p1.x;
                u1.y = fminf(fmaxf(v11 + 3.f, 0.f), 6.f) * (1.f / 6.f) * p1.y;
                *reinterpret_cast<float2*>(
                    &out[((size_t)b * CDIM + r0) * 4096 + hw]) = u0;
                *reinterpret_cast<float2*>(
                    &out[((size_t)b * CDIM + r1) * 4096 + hw]) = u1;
            } else {
                float2 u0, u1;
                u0.x = v00; u0.y = v01;
                u1.x = v10; u1.y = v11;
                *reinterpret_cast<float2*>(&out[(size_t)r0 * Nld + n0]) = u0;
                *reinterpret_cast<float2*>(&out[(size_t)r1 * Nld + n0]) = u1;
            }
        }
    }
}

// ---------------------------------------------------------------------------
// GEMM kernel wrappers (dynamic smem, 4 stages)
// Grid layout: (x = M-blocks, y = N-blocks) so CTAs sharing an N-slab of X
// are launch-adjacent -> X slab read hits L2 for all but the first.
// ---------------------------------------------------------------------------
template <int MODE>
__global__ void __launch_bounds__(256, 2)
tc_gemm(const float* __restrict__ Wm, const float* __restrict__ X,
        const float* __restrict__ scale, const float* __restrict__ bias,
        float* __restrict__ out, int K,
        const float* __restrict__ e0, const float* __restrict__ e1)
{
    extern __shared__ float dsm[];
    gemm_core<MODE>(Wm, X, scale, bias, out, K, e0, e1,
                    blockIdx.x * 128, blockIdx.y * 128, gridDim.y * 128,
                    dsm, dsm + NSTAGE * A_STAGE);
}

// batched q/k/v projection: z=0 -> q (M=128), z=1 -> k (M=128), z=2 -> v (M=512)
__global__ void __launch_bounds__(256, 2)
tc_gemm_qkv(const float* __restrict__ wq, const float* __restrict__ sq,
            const float* __restrict__ bq, float* __restrict__ oq,
            const float* __restrict__ wk, const float* __restrict__ sk,
            const float* __restrict__ bk, float* __restrict__ ok,
            const float* __restrict__ wv, const float* __restrict__ sv,
            const float* __restrict__ bv, float* __restrict__ ov,
            const float* __restrict__ X)
{
    extern __shared__ float dsm[];
    const int z = blockIdx.z;
    const int xv = (z < 2) ? 1 : 4;    // m-blocks valid for this z
    if ((int)blockIdx.x >= xv) return;
    const float* W = (z == 0) ? wq : (z == 1) ? wk : wv;
    const float* s = (z == 0) ? sq : (z == 1) ? sk : sv;
    const float* b = (z == 0) ? bq : (z == 1) ? bk : bv;
    float*       o = (z == 0) ? oq : (z == 1) ? ok : ov;
    gemm_core<0>(W, X, s, b, o, CDIM, nullptr, nullptr,
                 blockIdx.x * 128, blockIdx.y * 128, NAX2,
                 dsm, dsm + NSTAGE * A_STAGE);
}

// batched row/col cbn: z selects weight set + xx/rout slab
__global__ void __launch_bounds__(256, 2)
tc_gemm_rowcol(const float* __restrict__ w_row, const float* __restrict__ s_row,
               const float* __restrict__ b_row,
               const float* __restrict__ w_col, const float* __restrict__ s_col,
               const float* __restrict__ b_col,
               const float* __restrict__ xx, float* __restrict__ rout)
{
    extern __shared__ float dsm[];
    const int z = blockIdx.z;
    const float* W = z ? w_col : w_row;
    const float* s = z ? s_col : s_row;
    const float* b = z ? b_col : b_row;
    const float* X = xx + (size_t)z * DHD * NAX;
    float*       o = rout + (size_t)z * DHD * NAX;
    gemm_core<1>(W, X, s, b, o, DHD, nullptr, nullptr,
                 blockIdx.x * 128, blockIdx.y * 128, NAX,
                 dsm, dsm + NSTAGE * A_STAGE);
}

// ---------------------------------------------------------------------------
// K1: row/col means of x -> packed [256][2048] (axis 0 = row, axis 1 = col)
// ---------------------------------------------------------------------------
__global__ void mean_kernel(const float* __restrict__ x)
{
    __shared__ float s[64 * 65];
    const int blk = blockIdx.x;                // b*256 + c
    const float* base = x + (size_t)blk * 4096;
    const int t = threadIdx.x;                 // 64 threads

    #pragma unroll
    for (int i = 0; i < 64; i++) s[i * 65 + t] = base[i * 64 + t];
    __syncthreads();

    float rs = 0.f, cs = 0.f;
    #pragma unroll
    for (int i = 0; i < 64; i++) {
        rs += s[t * 65 + i];
        cs += s[i * 65 + t];
    }
    const int b = blk >> 8;
    const int c = blk & 255;
    g_xmean[c * NAX2 + b * 64 + t]        = rs * (1.f / 64.f);
    g_xmean[c * NAX2 + 1024 + b * 64 + t] = cs * (1.f / 64.f);
}

// ---------------------------------------------------------------------------
// K3: axial attention. One block per (axis, b, head); 64 threads.
// ---------------------------------------------------------------------------
__device__ __forceinline__ float pos_interp(const float* __restrict__ p,
                                            int ch, int i)
{
    float c = (i + 0.5f) * 0.25f - 0.5f;
    c = fminf(fmaxf(c, 0.f), 15.f);
    int lo = (int)floorf(c);
    int hi = min(lo + 1, 15);
    float tt = c - (float)lo;
    const float* row = p + ch * 16;
    return row[lo] * (1.f - tt) + row[hi] * tt;
}

__global__ void attn_kernel(const float* __restrict__ pos_rowq,
                            const float* __restrict__ pos_rowk,
                            const float* __restrict__ pos_colq,
                            const float* __restrict__ pos_colk)
{
    const int blk  = blockIdx.x;          // axis*128 + b*8 + head
    const int axis = blk >> 7;
    const int b    = (blk >> 3) & 15;
    const int head = blk & 7;
    const float* pq = axis ? pos_colq : pos_rowq;
    const float* pk = axis ? pos_colk : pos_rowk;
    const int col0 = axis * 1024 + b * 64;

    __shared__ float ks[KEYD][64];
    __shared__ float vs[DV][64];
    const int t = threadIdx.x;            // 64

    float qr[KEYD];
    #pragma unroll
    for (int c = 0; c < KEYD; c++) {
        const int ch = head * KEYD + c;
        ks[c][t] = g_ke[ch * NAX2 + col0 + t] + pos_interp(pk, ch, t);
        qr[c]    = g_qe[ch * NAX2 + col0 + t] + pos_interp(pq, ch, t);
    }
    #pragma unroll
    for (int d = 0; d < DV; d++)
        vs[d][t] = g_ve[(head * DV + d) * NAX2 + col0 + t];
    __syncthreads();

    float S[64];
    float mx = -1e30f;
    #pragma unroll
    for (int j = 0; j < 64; j++) {
        float s = 0.f;
        #pragma unroll
        for (int c = 0; c < KEYD; c++) s += qr[c] * ks[c][j];
        s *= ATTN_SCALE;
        S[j] = s;
        mx = fmaxf(mx, s);
    }
    float sum = 0.f;
    #pragma unroll
    for (int j = 0; j < 64; j++) { S[j] = __expf(S[j] - mx); sum += S[j]; }
    const float inv = 1.f / sum;

    float* xo = g_xx[axis];
    #pragma unroll
    for (int d = 0; d < DV; d++) {
        float o = 0.f;
        #pragma unroll
        for (int j = 0; j < 64; j++) o += S[j] * vs[d][j];
        xo[(head * DV + d) * NAX + b * 64 + t] = o * inv;
    }
}

// ---------------------------------------------------------------------------
// K6b: depthwise 3x3 (SAME, zero pad) + affine + relu.  g1 -> g2
// ---------------------------------------------------------------------------
__global__ void dw_kernel(const float* __restrict__ wdw,
                          const float* __restrict__ sdw,
                          const float* __restrict__ bdw)
{
    const long long idx = (long long)blockIdx.x * blockDim.x + threadIdx.x;
    if (idx >= (long long)CDIM * NPIX) return;
    const int n = (int)(idx & (NPIX - 1));
    const int c = (int)(idx >> 16);
    const int b = n >> 12, hw = n & 4095;
    const int h = hw >> 6, w = hw & 63;
    const float* base = g_g1 + (size_t)c * NPIX + (size_t)b * 4096;
    const float* wk = wdw + c * 9;

    float acc = 0.f;
    #pragma unroll
    for (int dy = 0; dy < 3; dy++) {
        const int hh = h + dy - 1;
        if (hh < 0 || hh > 63) continue;
        #pragma unroll
        for (int dx = 0; dx < 3; dx++) {
            const int ww = w + dx - 1;
            if (ww < 0 || ww > 63) continue;
            acc += base[hh * 64 + ww] * wk[dy * 3 + dx];
        }
    }
    float v = acc * sdw[c] + bdw[c];
    g_g2[idx] = fmaxf(v, 0.f);
}

// ---------------------------------------------------------------------------
// Host launcher. Two-stream fork/join: the gate chain (K5g -> dw) depends
// only on x, so it runs on s2 concurrently with the attention chain.
// ---------------------------------------------------------------------------
extern "C" void kernel_launch(void* const* d_in, const int* in_sizes, int n_in,
                              void* d_out, int out_size)
{
    const float* x        = (const float*)d_in[0];
    const float* wq       = (const float*)d_in[1];
    const float* sq       = (const float*)d_in[2];
    const float* bq       = (const float*)d_in[3];
    const float* wk       = (const float*)d_in[4];
    const float* sk       = (const float*)d_in[5];
    const float* bk       = (const float*)d_in[6];
    const float* wv       = (const float*)d_in[7];
    const float* sv       = (const float*)d_in[8];
    const float* bv       = (const float*)d_in[9];
    const float* pos_rowq = (const float*)d_in[10];
    const float* pos_rowk = (const float*)d_in[11];
    const float* pos_colq = (const float*)d_in[12];
    const float* pos_colk = (const float*)d_in[13];
    const float* w_row    = (const float*)d_in[14];
    const float* s_row    = (const float*)d_in[15];
    const float* b_row    = (const float*)d_in[16];
    const float* w_col    = (const float*)d_in[17];
    const float* s_col    = (const float*)d_in[18];
    const float* b_col    = (const float*)d_in[19];
    const float* w_proj   = (const float*)d_in[20];
    const float* s_proj   = (const float*)d_in[21];
    const float* b_proj   = (const float*)d_in[22];
    const float* w_sc     = (const float*)d_in[23];
    const float* s_sc     = (const float*)d_in[24];
    const float* b_sc     = (const float*)d_in[25];
    const float* w_dw     = (const float*)d_in[26];
    const float* s_dw     = (const float*)d_in[27];
    const float* b_dw     = (const float*)d_in[28];
    const float* w_pw     = (const float*)d_in[29];
    const float* s_pw     = (const float*)d_in[30];
    const float* b_pw     = (const float*)d_in[31];

    float *p_xm, *p_qe, *p_ke, *p_ve, *p_xx, *p_rout, *p_A, *p_g1, *p_g2, *p_P;
    cudaGetSymbolAddress((void**)&p_xm,   g_xmean);
    cudaGetSymbolAddress((void**)&p_qe,   g_qe);
    cudaGetSymbolAddress((void**)&p_ke,   g_ke);
    cudaGetSymbolAddress((void**)&p_ve,   g_ve);
    cudaGetSymbolAddress((void**)&p_xx,   g_xx);
    cudaGetSymbolAddress((void**)&p_rout, g_rout);
    cudaGetSymbolAddress((void**)&p_A,    g_A);
    cudaGetSymbolAddress((void**)&p_g1,   g_g1);
    cudaGetSymbolAddress((void**)&p_g2,   g_g2);
    cudaGetSymbolAddress((void**)&p_P,    g_P);

    static cudaStream_t s2 = nullptr;
    static cudaEvent_t evFork = nullptr, evJoin = nullptr;
    static int init_done = 0;
    if (!init_done) {
        cudaFuncSetAttribute(tc_gemm<0>, cudaFuncAttributeMaxDynamicSharedMemorySize, SMEM_SZ);
        cudaFuncSetAttribute(tc_gemm<2>, cudaFuncAttributeMaxDynamicSharedMemorySize, SMEM_SZ);
        cudaFuncSetAttribute(tc_gemm<3>, cudaFuncAttributeMaxDynamicSharedMemorySize, SMEM_SZ);
        cudaFuncSetAttribute(tc_gemm<4>, cudaFuncAttributeMaxDynamicSharedMemorySize, SMEM_SZ);
        cudaFuncSetAttribute(tc_gemm_qkv, cudaFuncAttributeMaxDynamicSharedMemorySize, SMEM_SZ);
        cudaFuncSetAttribute(tc_gemm_rowcol, cudaFuncAttributeMaxDynamicSharedMemorySize, SMEM_SZ);
        cudaStreamCreateWithFlags(&s2, cudaStreamNonBlocking);
        cudaEventCreateWithFlags(&evFork, cudaEventDisableTiming);
        cudaEventCreateWithFlags(&evJoin, cudaEventDisableTiming);
        init_done = 1;
    }

    // ---- fork: gate chain on s2 (depends only on x) ----
    cudaEventRecord(evFork, 0);
    cudaStreamWaitEvent(s2, evFork, 0);

    // K5g: g1 = cbn(x, w_sc)
    tc_gemm<3><<<dim3(2, 512), 256, SMEM_SZ, s2>>>(
        w_sc, x, s_sc, b_sc, p_g1, CDIM, nullptr, nullptr);
    // K6b: depthwise 3x3 + affine + relu
    dw_kernel<<<(CDIM * NPIX) / 256, 256, 0, s2>>>(w_dw, s_dw, b_dw);
    cudaEventRecord(evJoin, s2);

    // ---- main chain on default stream ----
    // K1: means (both axes into one [256][2048] buffer)
    mean_kernel<<<BB * CDIM, 64>>>(x);

    // K2: q/k/v projections, single batched launch (z = q,k,v)
    tc_gemm_qkv<<<dim3(4, NAX2 / 128, 3), 256, SMEM_SZ>>>(
        wq, sq, bq, p_qe, wk, sk, bk, p_ke, wv, sv, bv, p_ve, p_xm);

    // K3: axial attention (both axes)
    attn_kernel<<<2 * BB * NHEADS, 64>>>(pos_rowq, pos_rowk, pos_colq, pos_colk);

    // K4: w_row / w_col cbn on relu(xx), single batched launch
    tc_gemm_rowcol<<<dim3(DHD / 128, NAX / 128, 2), 256, SMEM_SZ>>>(
        w_row, s_row, b_row, w_col, s_col, b_col, p_xx, p_rout);

    // K5: A = relu(v + row + col)   (big GEMM over all pixels)
    tc_gemm<2><<<dim3(4, 512), 256, SMEM_SZ>>>(
        wv, x, sv, bv, p_A, CDIM, p_rout, p_rout + (size_t)DHD * NAX);

    // K6a: P = cbn(A, w_proj)
    tc_gemm<0><<<dim3(2, 512), 256, SMEM_SZ>>>(
        w_proj, p_A, s_proj, b_proj, p_P, DHD, nullptr, nullptr);

    // ---- join: K6c needs g2 (s2) and P (stream 0) ----
    cudaStreamWaitEvent(0, evJoin, 0);

    // K6c: out = h_sigmoid(cbn(g2, w_pw)) * P  (scatter to NCHW)
    tc_gemm<4><<<dim3(2, 512), 256, SMEM_SZ>>>(
        w_pw, p_g2, s_pw, b_pw, (float*)d_out, CDIM, p_P, nullptr);
}